// round 9
// baseline (speedup 1.0000x reference)
#include <cuda_runtime.h>
#include <cuda_bf16.h>
#include <cuda_fp16.h>
#include <cstdint>

// ===========================================================================
// VQ-VAE forward on GB300:
//   encoder  : fp16 2-plane HMMA (fast, ~1e-7-accurate values)
//   VQ       : fp32 distances from TC z + best2 gap test -> flags
//   repair   : flagged rows recomputed in EXACT fp32 (bit-identical to the
//              proven round-1 sequential-k path), argmin redone exactly
//   decoder  : bf16 HMMA 2-plane 3-product fused (proven round-7, unchanged)
// ===========================================================================

#define M_ROWS 8192
#define EMB_NUM 1024
#define EMB_DIM 64
#define FLAG_T 1e-7f

typedef unsigned long long u64;
typedef __nv_bfloat16 bf16;
typedef __half f16;

// ---------------------------------------------------------------------------
// Static device scratch (allocation-free rule)
// ---------------------------------------------------------------------------
__device__ f16  g_xh[8192 * 2048];
__device__ f16  g_xm[8192 * 2048];
__device__ f16  g_w0h[1024 * 2048];
__device__ f16  g_w0m[1024 * 2048];
__device__ f16  g_w1h[512 * 1024];
__device__ f16  g_w1m[512 * 1024];
__device__ f16  g_h1h[8192 * 1024];
__device__ f16  g_h1m[8192 * 1024];
__device__ float g_h2[8192 * 512];
__device__ float g_z [8192 * 256];
__device__ float g_cn[EMB_NUM];
__device__ int   g_flags[32768];
__device__ bf16 g_zq[2][8192 * 256];
__device__ bf16 g_d1[2][8192 * 512];
__device__ bf16 g_d2[2][8192 * 1024];
__device__ bf16 g_wd0[2][512 * 256];
__device__ bf16 g_wd1[2][1024 * 512];
__device__ bf16 g_wo[2][2048 * 1024];

// ---------------------------------------------------------------------------
// PTX helpers
// ---------------------------------------------------------------------------
__device__ __forceinline__ uint32_t smem_u32(const void* p) {
    uint32_t a;
    asm("{ .reg .u64 t; cvta.to.shared.u64 t, %1; cvt.u32.u64 %0, t; }" : "=r"(a) : "l"(p));
    return a;
}
__device__ __forceinline__ void cp16(uint32_t dst, const void* src) {
    asm volatile("cp.async.cg.shared.global [%0], [%1], 16;" :: "r"(dst), "l"(src));
}
#define CP_COMMIT() asm volatile("cp.async.commit_group;" ::: "memory")
#define CP_WAIT0()  asm volatile("cp.async.wait_group 0;" ::: "memory")

__device__ __forceinline__ void ldm_x4(uint32_t r[4], uint32_t addr) {
    asm volatile("ldmatrix.sync.aligned.m8n8.x4.shared.b16 {%0,%1,%2,%3}, [%4];"
                 : "=r"(r[0]), "=r"(r[1]), "=r"(r[2]), "=r"(r[3]) : "r"(addr));
}
__device__ __forceinline__ void mma_bf16(float* d, const uint32_t* a, uint32_t b0, uint32_t b1) {
    asm volatile(
        "mma.sync.aligned.m16n8k16.row.col.f32.bf16.bf16.f32 "
        "{%0,%1,%2,%3}, {%4,%5,%6,%7}, {%8,%9}, {%0,%1,%2,%3};"
        : "+f"(d[0]), "+f"(d[1]), "+f"(d[2]), "+f"(d[3])
        : "r"(a[0]), "r"(a[1]), "r"(a[2]), "r"(a[3]), "r"(b0), "r"(b1));
}
__device__ __forceinline__ void mma_f16(float* d, const uint32_t* a, uint32_t b0, uint32_t b1) {
    asm volatile(
        "mma.sync.aligned.m16n8k16.row.col.f32.f16.f16.f32 "
        "{%0,%1,%2,%3}, {%4,%5,%6,%7}, {%8,%9}, {%0,%1,%2,%3};"
        : "+f"(d[0]), "+f"(d[1]), "+f"(d[2]), "+f"(d[3])
        : "r"(a[0]), "r"(a[1]), "r"(a[2]), "r"(a[3]), "r"(b0), "r"(b1));
}
__device__ __forceinline__ u64 pack2f(float lo, float hi) {
    u64 r; asm("mov.b64 %0, {%1, %2};" : "=l"(r) : "f"(lo), "f"(hi)); return r;
}
__device__ __forceinline__ void unpack2f(u64 v, float& lo, float& hi) {
    asm("mov.b64 {%0, %1}, %2;" : "=f"(lo), "=f"(hi) : "l"(v));
}
__device__ __forceinline__ u64 ffma2(u64 a, u64 b, u64 c) {
    u64 d; asm("fma.rn.f32x2 %0, %1, %2, %3;" : "=l"(d) : "l"(a), "l"(b), "l"(c)); return d;
}

// ---------------------------------------------------------------------------
// fp32 tiled SGEMM (exact; used for z layer)
// ---------------------------------------------------------------------------
template <int BM, int BN, int BK, int TM, int TN, bool RELU>
__global__ __launch_bounds__((BM / TM) * (BN / TN))
void gemm_bias_kernel(const float* __restrict__ A,
                      const float* __restrict__ W,
                      const float* __restrict__ bias,
                      float* __restrict__ C,
                      int M, int N, int K) {
    constexpr int THREADS = (BM / TM) * (BN / TN);
    constexpr int PAD = 4;
    __shared__ float As[BK][BM + PAD];
    __shared__ float Ws[BK][BN + PAD];

    const int bm = blockIdx.y * BM;
    const int bn = blockIdx.x * BN;
    const int tid = threadIdx.x;
    const int tx = tid % (BN / TN);
    const int ty = tid / (BN / TN);

    float acc[TM][TN];
#pragma unroll
    for (int i = 0; i < TM; i++)
#pragma unroll
        for (int j = 0; j < TN; j++) acc[i][j] = 0.0f;

    for (int k0 = 0; k0 < K; k0 += BK) {
#pragma unroll
        for (int i = tid; i < BM * BK / 4; i += THREADS) {
            int r  = i / (BK / 4);
            int c4 = i % (BK / 4);
            float4 v = *reinterpret_cast<const float4*>(A + (size_t)(bm + r) * K + k0 + c4 * 4);
            As[c4 * 4 + 0][r] = v.x;
            As[c4 * 4 + 1][r] = v.y;
            As[c4 * 4 + 2][r] = v.z;
            As[c4 * 4 + 3][r] = v.w;
        }
#pragma unroll
        for (int i = tid; i < BN * BK / 4; i += THREADS) {
            int r  = i / (BK / 4);
            int c4 = i % (BK / 4);
            float4 v = *reinterpret_cast<const float4*>(W + (size_t)(bn + r) * K + k0 + c4 * 4);
            Ws[c4 * 4 + 0][r] = v.x;
            Ws[c4 * 4 + 1][r] = v.y;
            Ws[c4 * 4 + 2][r] = v.z;
            Ws[c4 * 4 + 3][r] = v.w;
        }
        __syncthreads();

#pragma unroll
        for (int k = 0; k < BK; k++) {
            float a[TM], b[TN];
            *reinterpret_cast<float4*>(&a[0]) = *reinterpret_cast<const float4*>(&As[k][ty * TM + 0]);
            *reinterpret_cast<float4*>(&a[4]) = *reinterpret_cast<const float4*>(&As[k][ty * TM + 4]);
            *reinterpret_cast<float4*>(&b[0]) = *reinterpret_cast<const float4*>(&Ws[k][tx * TN + 0]);
            *reinterpret_cast<float4*>(&b[4]) = *reinterpret_cast<const float4*>(&Ws[k][tx * TN + 4]);
#pragma unroll
            for (int i = 0; i < TM; i++)
#pragma unroll
                for (int j = 0; j < TN; j++)
                    acc[i][j] = fmaf(a[i], b[j], acc[i][j]);
        }
        __syncthreads();
    }

    float bv[TN];
#pragma unroll
    for (int j = 0; j < TN; j++) bv[j] = bias[bn + tx * TN + j];

#pragma unroll
    for (int i = 0; i < TM; i++) {
        int row = bm + ty * TM + i;
        float out[TN];
#pragma unroll
        for (int j = 0; j < TN; j++) {
            float v = acc[i][j] + bv[j];
            if (RELU) v = fmaxf(v, 0.0f);
            out[j] = v;
        }
        float* cptr = C + (size_t)row * N + bn + tx * TN;
        *reinterpret_cast<float4*>(cptr + 0) = *reinterpret_cast<float4*>(&out[0]);
        *reinterpret_cast<float4*>(cptr + 4) = *reinterpret_cast<float4*>(&out[4]);
    }
}

// ---------------------------------------------------------------------------
// Shared tile geometry for HMMA kernels
// ---------------------------------------------------------------------------
#define DEC_TILE_B  10240
#define DEC_STAGE_B (4 * DEC_TILE_B)
#define DEC_SMEM    (2 * DEC_STAGE_B)

// ---------------------------------------------------------------------------
// ENCODER h1/h2: fp16 2-plane (m-plane pre-scaled x4096), 3 products.
// ---------------------------------------------------------------------------
template <bool RELU, bool OUTPLANES>
__global__ __launch_bounds__(256, 1)
void enc_hmma_kernel(const f16* __restrict__ Ah, const f16* __restrict__ Am,
                     const f16* __restrict__ Bh, const f16* __restrict__ Bm,
                     const float* __restrict__ bias,
                     float* __restrict__ Cf,
                     f16* __restrict__ Ch, f16* __restrict__ Cm,
                     int N, int K) {
    extern __shared__ char dsm[];
    const uint32_t su = smem_u32(dsm);

    const int tid = threadIdx.x;
    const int wid = tid >> 5, lane = tid & 31;
    const int wm = wid >> 2, wn = wid & 3;
    const int bn = blockIdx.x * 128, bm = blockIdx.y * 128;
    const int KC = K >> 5;

    const f16* P[4] = { Ah + (size_t)bm * K, Am + (size_t)bm * K,
                        Bh + (size_t)bn * K, Bm + (size_t)bn * K };

    float accA[4][4][4], accB[4][4][4];
#pragma unroll
    for (int i = 0; i < 4; i++)
#pragma unroll
        for (int j = 0; j < 4; j++)
#pragma unroll
            for (int q = 0; q < 4; q++) { accA[i][j][q] = 0.0f; accB[i][j][q] = 0.0f; }

    auto load_chunk = [&](int stage, int k0) {
#pragma unroll
        for (int t = 0; t < 4; t++) {
            const f16* src = P[t];
#pragma unroll
            for (int j = 0; j < 2; j++) {
                int ch = j * 256 + tid;
                int r = ch >> 2, cc = ch & 3;
                uint32_t off = (uint32_t)((stage * 4 + t) * DEC_TILE_B + r * 80 + cc * 16);
                cp16(su + off, src + (size_t)r * K + k0 + cc * 8);
            }
        }
        CP_COMMIT();
    };

    load_chunk(0, 0);

    const int tA[3] = {0, 0, 1};
    const int tB[3] = {2, 3, 2};

    for (int c = 0; c < KC; c++) {
        CP_WAIT0();
        __syncthreads();
        if (c + 1 < KC) load_chunk((c + 1) & 1, (c + 1) << 5);

        const int stage = c & 1;
#pragma unroll
        for (int p = 0; p < 3; p++) {
            const uint32_t baseA = su + (uint32_t)((stage * 4 + tA[p]) * DEC_TILE_B);
            const uint32_t baseB = su + (uint32_t)((stage * 4 + tB[p]) * DEC_TILE_B);
            float (*acc)[4][4] = (p == 0) ? accA : accB;
#pragma unroll
            for (int ks = 0; ks < 2; ks++) {
                uint32_t af[4][4], bg[2][4];
#pragma unroll
                for (int mt = 0; mt < 4; mt++) {
                    uint32_t addr = baseA + (uint32_t)((wm * 64 + mt * 16 + ((lane >> 3) & 1) * 8 + (lane & 7)) * 80
                                                       + (ks * 16 + (lane >> 4) * 8) * 2);
                    ldm_x4(af[mt], addr);
                }
#pragma unroll
                for (int np = 0; np < 2; np++) {
                    uint32_t addr = baseB + (uint32_t)((wn * 32 + np * 16 + ((lane >> 4) & 1) * 8 + (lane & 7)) * 80
                                                       + (ks * 16 + ((lane >> 3) & 1) * 8) * 2);
                    ldm_x4(bg[np], addr);
                }
#pragma unroll
                for (int mt = 0; mt < 4; mt++)
#pragma unroll
                    for (int nt = 0; nt < 4; nt++)
                        mma_f16(acc[mt][nt], af[mt], bg[nt >> 1][(nt & 1) * 2], bg[nt >> 1][(nt & 1) * 2 + 1]);
            }
        }
        __syncthreads();
    }

    const float SINV = 1.0f / 4096.0f;
#pragma unroll
    for (int mt = 0; mt < 4; mt++) {
#pragma unroll
        for (int nt = 0; nt < 4; nt++) {
            const int r0 = bm + wm * 64 + mt * 16 + (lane >> 2);
            const int c0 = bn + wn * 32 + nt * 8 + (lane & 3) * 2;
            const float bv0 = bias[c0], bv1 = bias[c0 + 1];
#pragma unroll
            for (int h = 0; h < 2; h++) {
                const int r = r0 + h * 8;
                float v0 = fmaf(accB[mt][nt][h * 2 + 0], SINV, accA[mt][nt][h * 2 + 0]) + bv0;
                float v1 = fmaf(accB[mt][nt][h * 2 + 1], SINV, accA[mt][nt][h * 2 + 1]) + bv1;
                if (RELU) { v0 = fmaxf(v0, 0.0f); v1 = fmaxf(v1, 0.0f); }
                const size_t o = (size_t)r * N + c0;
                if (!OUTPLANES) {
                    *reinterpret_cast<float2*>(Cf + o) = make_float2(v0, v1);
                } else {
                    f16 h0 = __float2half_rn(v0), h1v = __float2half_rn(v1);
                    float r0f = (v0 - __half2float(h0)) * 4096.0f;
                    float r1f = (v1 - __half2float(h1v)) * 4096.0f;
                    __half2 hp; hp.x = h0; hp.y = h1v;
                    __half2 mp; mp.x = __float2half_rn(r0f); mp.y = __float2half_rn(r1f);
                    *reinterpret_cast<__half2*>(Ch + o) = hp;
                    *reinterpret_cast<__half2*>(Cm + o) = mp;
                }
            }
        }
    }
}

// ---------------------------------------------------------------------------
// DECODER: bf16 HMMA, 2-plane, 3-product fused (byte-identical to round 7)
// ---------------------------------------------------------------------------
template <bool RELU, int OUTP>
__global__ __launch_bounds__(256, 2)
void gemm_hmma_kernel(const bf16* __restrict__ A0, const bf16* __restrict__ A1,
                      const bf16* __restrict__ B0, const bf16* __restrict__ B1,
                      const float* __restrict__ bias,
                      float* __restrict__ Cf,
                      bf16* __restrict__ Ch, bf16* __restrict__ Cm,
                      int N, int K) {
    extern __shared__ char dsm[];
    const uint32_t su = smem_u32(dsm);

    const int tid = threadIdx.x;
    const int wid = tid >> 5, lane = tid & 31;
    const int wm = wid >> 2, wn = wid & 3;
    const int bn = blockIdx.x * 128, bm = blockIdx.y * 128;
    const int KC = K >> 5;

    const bf16* P[4] = { A0 + (size_t)bm * K, A1 + (size_t)bm * K,
                         B0 + (size_t)bn * K, B1 + (size_t)bn * K };

    float acc[4][4][4];
#pragma unroll
    for (int i = 0; i < 4; i++)
#pragma unroll
        for (int j = 0; j < 4; j++)
#pragma unroll
            for (int q = 0; q < 4; q++) acc[i][j][q] = 0.0f;

    auto load_chunk = [&](int stage, int k0) {
#pragma unroll
        for (int t = 0; t < 4; t++) {
            const bf16* src = P[t];
#pragma unroll
            for (int j = 0; j < 2; j++) {
                int ch = j * 256 + tid;
                int r = ch >> 2, cc = ch & 3;
                uint32_t off = (uint32_t)((stage * 4 + t) * DEC_TILE_B + r * 80 + cc * 16);
                cp16(su + off, src + (size_t)r * K + k0 + cc * 8);
            }
        }
        CP_COMMIT();
    };

    load_chunk(0, 0);

    const int tA[3] = {0, 0, 1};
    const int tB[3] = {2, 3, 2};

    for (int c = 0; c < KC; c++) {
        CP_WAIT0();
        __syncthreads();
        if (c + 1 < KC) load_chunk((c + 1) & 1, (c + 1) << 5);

        const int stage = c & 1;
#pragma unroll
        for (int p = 0; p < 3; p++) {
            const uint32_t baseA = su + (uint32_t)((stage * 4 + tA[p]) * DEC_TILE_B);
            const uint32_t baseB = su + (uint32_t)((stage * 4 + tB[p]) * DEC_TILE_B);
#pragma unroll
            for (int ks = 0; ks < 2; ks++) {
                uint32_t af[4][4], bg[2][4];
#pragma unroll
                for (int mt = 0; mt < 4; mt++) {
                    uint32_t addr = baseA + (uint32_t)((wm * 64 + mt * 16 + ((lane >> 3) & 1) * 8 + (lane & 7)) * 80
                                                       + (ks * 16 + (lane >> 4) * 8) * 2);
                    ldm_x4(af[mt], addr);
                }
#pragma unroll
                for (int np = 0; np < 2; np++) {
                    uint32_t addr = baseB + (uint32_t)((wn * 32 + np * 16 + ((lane >> 4) & 1) * 8 + (lane & 7)) * 80
                                                       + (ks * 16 + ((lane >> 3) & 1) * 8) * 2);
                    ldm_x4(bg[np], addr);
                }
#pragma unroll
                for (int mt = 0; mt < 4; mt++)
#pragma unroll
                    for (int nt = 0; nt < 4; nt++)
                        mma_bf16(acc[mt][nt], af[mt], bg[nt >> 1][(nt & 1) * 2], bg[nt >> 1][(nt & 1) * 2 + 1]);
            }
        }
        __syncthreads();
    }

#pragma unroll
    for (int mt = 0; mt < 4; mt++) {
#pragma unroll
        for (int nt = 0; nt < 4; nt++) {
            const int r0 = bm + wm * 64 + mt * 16 + (lane >> 2);
            const int c0 = bn + wn * 32 + nt * 8 + (lane & 3) * 2;
            const float bv0 = bias[c0], bv1 = bias[c0 + 1];
#pragma unroll
            for (int h = 0; h < 2; h++) {
                const int r = r0 + h * 8;
                float v0 = acc[mt][nt][h * 2 + 0] + bv0;
                float v1 = acc[mt][nt][h * 2 + 1] + bv1;
                if (RELU) { v0 = fmaxf(v0, 0.0f); v1 = fmaxf(v1, 0.0f); }
                const size_t o = (size_t)r * N + c0;
                if (OUTP == 0) {
                    *reinterpret_cast<float2*>(Cf + o) = make_float2(v0, v1);
                } else {
                    bf16 h0 = __float2bfloat16(v0), h1v = __float2bfloat16(v1);
                    float r0f = v0 - __bfloat162float(h0);
                    float r1f = v1 - __bfloat162float(h1v);
                    __nv_bfloat162 hp; hp.x = h0; hp.y = h1v;
                    __nv_bfloat162 mp; mp.x = __float2bfloat16(r0f); mp.y = __float2bfloat16(r1f);
                    *reinterpret_cast<__nv_bfloat162*>(Ch + o) = hp;
                    *reinterpret_cast<__nv_bfloat162*>(Cm + o) = mp;
                }
            }
        }
    }
}

// ---------------------------------------------------------------------------
// Splits
// ---------------------------------------------------------------------------
__global__ void split2h_kernel(const float* __restrict__ src,
                               f16* __restrict__ h, f16* __restrict__ m, int n) {
    int i = blockIdx.x * blockDim.x + threadIdx.x;
    if (i < n) {
        float v = src[i];
        f16 a = __float2half_rn(v);
        float r1 = (v - __half2float(a)) * 4096.0f;
        h[i] = a; m[i] = __float2half_rn(r1);
    }
}
__global__ void split2_kernel(const float* __restrict__ src,
                              bf16* __restrict__ h, bf16* __restrict__ m, int n) {
    int i = blockIdx.x * blockDim.x + threadIdx.x;
    if (i < n) {
        float v = src[i];
        bf16 a = __float2bfloat16(v);
        float r1 = v - __bfloat162float(a);
        h[i] = a; m[i] = __float2bfloat16(r1);
    }
}

// ---------------------------------------------------------------------------
// Codebook squared norms
// ---------------------------------------------------------------------------
__global__ void cnorm_kernel(const float* __restrict__ cb, float* __restrict__ cn) {
    int i = blockIdx.x * blockDim.x + threadIdx.x;
    if (i >= EMB_NUM) return;
    const float4* p = reinterpret_cast<const float4*>(cb + (size_t)i * EMB_DIM);
    float s = 0.0f;
#pragma unroll
    for (int d = 0; d < EMB_DIM / 4; d++) {
        float4 v = p[d];
        s += v.x * v.x + v.y * v.y + v.z * v.z + v.w * v.w;
    }
    cn[i] = s;
}

// ---------------------------------------------------------------------------
// VQ with gap test: fp32 distances from TC z; flag groups with tiny gaps.
// ---------------------------------------------------------------------------
__global__ __launch_bounds__(256)
void vq_kernel(const float* __restrict__ z,
               const float* __restrict__ cb,
               const float* __restrict__ cn,
               bf16* __restrict__ qh, bf16* __restrict__ qm,
               int* __restrict__ flags) {
    constexpr int CHUNK = 128;
    __shared__ float sc[CHUNK][EMB_DIM];
    __shared__ float scn[CHUNK];

    const int row = blockIdx.x * blockDim.x + threadIdx.x;
    const float* zp = z + (size_t)row * EMB_DIM;

    u64 m2zP[EMB_DIM / 2];
#pragma unroll
    for (int d = 0; d < EMB_DIM / 4; d++) {
        float4 v = reinterpret_cast<const float4*>(zp)[d];
        m2zP[d * 2 + 0] = pack2f(-2.0f * v.x, -2.0f * v.y);
        m2zP[d * 2 + 1] = pack2f(-2.0f * v.z, -2.0f * v.w);
    }

    float best = 3.0e38f, best2 = 3.0e38f;
    int bidx = 0;
    for (int ch = 0; ch < EMB_NUM / CHUNK; ch++) {
        __syncthreads();
        const float4* src = reinterpret_cast<const float4*>(cb + (size_t)ch * CHUNK * EMB_DIM);
        float4* dst = reinterpret_cast<float4*>(&sc[0][0]);
        for (int i = threadIdx.x; i < CHUNK * EMB_DIM / 4; i += 256) dst[i] = src[i];
        if (threadIdx.x < CHUNK) scn[threadIdx.x] = cn[ch * CHUNK + threadIdx.x];
        __syncthreads();

        for (int j = 0; j < CHUNK; j++) {
            u64 sP = 0ull;
#pragma unroll
            for (int d = 0; d < EMB_DIM / 4; d++) {
                float4 cc = reinterpret_cast<const float4*>(&sc[j][0])[d];
                sP = ffma2(pack2f(cc.x, cc.y), m2zP[d * 2 + 0], sP);
                sP = ffma2(pack2f(cc.z, cc.w), m2zP[d * 2 + 1], sP);
            }
            float lo, hi;
            unpack2f(sP, lo, hi);
            float s = scn[j] + lo + hi;
            if (s < best) { best2 = best; best = s; bidx = ch * CHUNK + j; }
            else if (s < best2) { best2 = s; }
        }
    }

    flags[row] = (best2 - best < FLAG_T) ? 1 : 0;

    const float* cp = cb + (size_t)bidx * EMB_DIM;
#pragma unroll
    for (int d = 0; d < EMB_DIM; d++) {
        float zz = zp[d];
        float v = zz + (cp[d] - zz);
        bf16 a = __float2bfloat16(v);
        float r1 = v - __bfloat162float(a);
        size_t o = (size_t)row * EMB_DIM + d;
        qh[o] = a; qm[o] = __float2bfloat16(r1);
    }
}

// ---------------------------------------------------------------------------
// REPAIR: for flagged z-rows, recompute h1/h2/z in exact sequential-k fp32
// (bit-identical to the proven fp32 path), redo argmin exactly (lowest-index
// tie-break = jnp.argmin first-occurrence), overwrite zq planes.
// ---------------------------------------------------------------------------
__global__ __launch_bounds__(256)
void repair_kernel(const float* __restrict__ x,
                   const float* __restrict__ w0, const float* __restrict__ b0,
                   const float* __restrict__ w1, const float* __restrict__ b1,
                   const float* __restrict__ zw, const float* __restrict__ zb,
                   const float* __restrict__ cb, const float* __restrict__ cn,
                   const int* __restrict__ flags,
                   bf16* __restrict__ qh, bf16* __restrict__ qm) {
    const int row = blockIdx.x;
    const int f0 = flags[row * 4 + 0], f1 = flags[row * 4 + 1];
    const int f2 = flags[row * 4 + 2], f3 = flags[row * 4 + 3];
    if (!(f0 | f1 | f2 | f3)) return;

    __shared__ float h1s[1024];
    __shared__ float h2s[512];
    __shared__ float zs[256];
    __shared__ float rbest[256];
    __shared__ int ridx[256];

    const int t = threadIdx.x;
    const float* xr = x + (size_t)row * 2048;

    // exact h1 row (ascending-k fmaf == proven fp32 path ordering)
    for (int o = t; o < 1024; o += 256) {
        const float* wr = w0 + (size_t)o * 2048;
        float acc = 0.0f;
        for (int k = 0; k < 2048; k++) acc = fmaf(xr[k], wr[k], acc);
        h1s[o] = fmaxf(acc + b0[o], 0.0f);
    }
    __syncthreads();
    // exact h2 row
    for (int o = t; o < 512; o += 256) {
        const float* wr = w1 + (size_t)o * 1024;
        float acc = 0.0f;
        for (int k = 0; k < 1024; k++) acc = fmaf(h1s[k], wr[k], acc);
        h2s[o] = fmaxf(acc + b1[o], 0.0f);
    }
    __syncthreads();
    // exact z row
    {
        const float* wr = zw + (size_t)t * 512;
        float acc = 0.0f;
        for (int k = 0; k < 512; k++) acc = fmaf(h2s[k], wr[k], acc);
        zs[t] = acc + zb[t];
    }
    __syncthreads();

    const int gf[4] = {f0, f1, f2, f3};
#pragma unroll
    for (int g = 0; g < 4; g++) {
        if (!gf[g]) continue;
        const float* zg = zs + g * EMB_DIM;
        // same distance formula as vq_kernel (exact fp32 z)
        u64 m2zP[EMB_DIM / 2];
#pragma unroll
        for (int d = 0; d < EMB_DIM / 4; d++) {
            float4 v = *reinterpret_cast<const float4*>(zg + d * 4);
            m2zP[d * 2 + 0] = pack2f(-2.0f * v.x, -2.0f * v.y);
            m2zP[d * 2 + 1] = pack2f(-2.0f * v.z, -2.0f * v.w);
        }
        float best = 3.0e38f;
        int bidx = 0;
        for (int jj = 0; jj < 4; jj++) {
            int j = jj * 256 + t;
            u64 sP = 0ull;
            const float4* cc4 = reinterpret_cast<const float4*>(cb + (size_t)j * EMB_DIM);
#pragma unroll
            for (int d = 0; d < EMB_DIM / 4; d++) {
                float4 cc = cc4[d];
                sP = ffma2(pack2f(cc.x, cc.y), m2zP[d * 2 + 0], sP);
                sP = ffma2(pack2f(cc.z, cc.w), m2zP[d * 2 + 1], sP);
            }
            float lo, hi;
            unpack2f(sP, lo, hi);
            float s = cn[j] + lo + hi;
            if (s < best || (s == best && j < bidx)) { best = s; bidx = j; }
        }
        rbest[t] = best; ridx[t] = bidx;
        __syncthreads();
        for (int s2 = 128; s2 > 0; s2 >>= 1) {
            if (t < s2) {
                float ob = rbest[t + s2]; int oi = ridx[t + s2];
                if (ob < rbest[t] || (ob == rbest[t] && oi < ridx[t])) { rbest[t] = ob; ridx[t] = oi; }
            }
            __syncthreads();
        }
        const int fin = ridx[0];
        if (t < EMB_DIM) {
            float zz = zg[t];
            float v = zz + (cb[(size_t)fin * EMB_DIM + t] - zz);
            bf16 a = __float2bfloat16(v);
            float r1 = v - __bfloat162float(a);
            size_t o = ((size_t)row * 4 + g) * EMB_DIM + t;
            qh[o] = a; qm[o] = __float2bfloat16(r1);
        }
        __syncthreads();
    }
}

// ---------------------------------------------------------------------------
// Host launch
// ---------------------------------------------------------------------------
template <bool RELU, bool OUTPLANES>
static inline void launch_encH(const f16* Ah, const f16* Am,
                               const f16* Bh, const f16* Bm,
                               const float* bias, float* Cf, f16* Ch, f16* Cm,
                               int N, int K) {
    cudaFuncSetAttribute(enc_hmma_kernel<RELU, OUTPLANES>,
                         cudaFuncAttributeMaxDynamicSharedMemorySize, DEC_SMEM);
    dim3 grid(N / 128, M_ROWS / 128);
    enc_hmma_kernel<RELU, OUTPLANES><<<grid, 256, DEC_SMEM>>>(Ah, Am, Bh, Bm, bias, Cf, Ch, Cm, N, K);
}

template <bool RELU, int OUTP>
static inline void launch_dec(const bf16* A0, const bf16* A1,
                              const bf16* B0, const bf16* B1,
                              const float* bias, float* Cf, bf16* Ch, bf16* Cm,
                              int N, int K) {
    cudaFuncSetAttribute(gemm_hmma_kernel<RELU, OUTP>,
                         cudaFuncAttributeMaxDynamicSharedMemorySize, DEC_SMEM);
    dim3 grid(N / 128, M_ROWS / 128);
    gemm_hmma_kernel<RELU, OUTP><<<grid, 256, DEC_SMEM>>>(A0, A1, B0, B1, bias, Cf, Ch, Cm, N, K);
}

extern "C" void kernel_launch(void* const* d_in, const int* in_sizes, int n_in,
                              void* d_out, int out_size) {
    const float* x        = (const float*)d_in[0];
    const float* enc0_w   = (const float*)d_in[1];
    const float* enc0_b   = (const float*)d_in[2];
    const float* enc1_w   = (const float*)d_in[3];
    const float* enc1_b   = (const float*)d_in[4];
    const float* z_w      = (const float*)d_in[5];
    const float* z_b      = (const float*)d_in[6];
    const float* codebook = (const float*)d_in[7];
    const float* dec0_w   = (const float*)d_in[8];
    const float* dec0_b   = (const float*)d_in[9];
    const float* dec1_w   = (const float*)d_in[10];
    const float* dec1_b   = (const float*)d_in[11];
    const float* out_w    = (const float*)d_in[12];
    const float* out_b    = (const float*)d_in[13];
    float* out = (float*)d_out;

    f16 *xh, *xm, *w0h, *w0m, *w1h, *w1m, *h1h, *h1m;
    cudaGetSymbolAddress((void**)&xh, g_xh);
    cudaGetSymbolAddress((void**)&xm, g_xm);
    cudaGetSymbolAddress((void**)&w0h, g_w0h);
    cudaGetSymbolAddress((void**)&w0m, g_w0m);
    cudaGetSymbolAddress((void**)&w1h, g_w1h);
    cudaGetSymbolAddress((void**)&w1m, g_w1m);
    cudaGetSymbolAddress((void**)&h1h, g_h1h);
    cudaGetSymbolAddress((void**)&h1m, g_h1m);
    float *h2, *z, *cn;
    int* flags;
    cudaGetSymbolAddress((void**)&h2, g_h2);
    cudaGetSymbolAddress((void**)&z,  g_z);
    cudaGetSymbolAddress((void**)&cn, g_cn);
    cudaGetSymbolAddress((void**)&flags, g_flags);
    bf16 (*zq)[8192 * 256];   cudaGetSymbolAddress((void**)&zq, g_zq);
    bf16 (*d1)[8192 * 512];   cudaGetSymbolAddress((void**)&d1, g_d1);
    bf16 (*d2)[8192 * 1024];  cudaGetSymbolAddress((void**)&d2, g_d2);
    bf16 (*wd0)[512 * 256];   cudaGetSymbolAddress((void**)&wd0, g_wd0);
    bf16 (*wd1)[1024 * 512];  cudaGetSymbolAddress((void**)&wd1, g_wd1);
    bf16 (*wo)[2048 * 1024];  cudaGetSymbolAddress((void**)&wo, g_wo);

    // splits
    split2h_kernel<<<(8192 * 2048 + 255) / 256, 256>>>(x, xh, xm, 8192 * 2048);
    split2h_kernel<<<(1024 * 2048 + 255) / 256, 256>>>(enc0_w, w0h, w0m, 1024 * 2048);
    split2h_kernel<<<(512 * 1024 + 255) / 256, 256>>>(enc1_w, w1h, w1m, 512 * 1024);
    split2_kernel<<<(512 * 256 + 255) / 256, 256>>>(dec0_w, wd0[0], wd0[1], 512 * 256);
    split2_kernel<<<(1024 * 512 + 255) / 256, 256>>>(dec1_w, wd1[0], wd1[1], 1024 * 512);
    split2_kernel<<<(2048 * 1024 + 255) / 256, 256>>>(out_w, wo[0], wo[1], 2048 * 1024);

    // encoder: h1, h2 via fp16 HMMA; z fp32 from h2
    launch_encH<true, true >(xh, xm, w0h, w0m, enc0_b, nullptr, h1h, h1m, 1024, 2048);
    launch_encH<true, false>(h1h, h1m, w1h, w1m, enc1_b, h2, nullptr, nullptr, 512, 1024);
    {
        dim3 grid(256 / 128, M_ROWS / 128);
        gemm_bias_kernel<128, 128, 16, 8, 8, false><<<grid, 256>>>(h2, z_w, z_b, z, M_ROWS, 256, 512);
    }

    // vector quantization with gap test, then exact repair of flagged rows
    cnorm_kernel<<<4, 256>>>(codebook, cn);
    vq_kernel<<<(M_ROWS * 256 / EMB_DIM) / 256, 256>>>(z, codebook, cn, zq[0], zq[1], flags);
    repair_kernel<<<M_ROWS, 256>>>(x, enc0_w, enc0_b, enc1_w, enc1_b, z_w, z_b,
                                   codebook, cn, flags, zq[0], zq[1]);

    // decoder (unchanged)
    launch_dec<true,  2>(zq[0], zq[1], wd0[0], wd0[1], dec0_b, nullptr, d1[0], d1[1], 512, 256);
    launch_dec<true,  2>(d1[0], d1[1], wd1[0], wd1[1], dec1_b, nullptr, d2[0], d2[1], 1024, 512);
    launch_dec<false, 0>(d2[0], d2[1], wo[0], wo[1],  out_b,  out, nullptr, nullptr, 2048, 1024);
}

// round 10
// speedup vs baseline: 2.5708x; 2.5708x over previous
#include <cuda_runtime.h>
#include <cuda_bf16.h>
#include <cuda_fp16.h>
#include <cstdint>

// ===========================================================================
// VQ-VAE forward on GB300:
//   encoder  : fp16 2-plane HMMA (fast, ~1e-7-accurate values)
//   VQ       : fp32 distances from TC z + best2 gap test -> flags (T=1e-8)
//   repair   : flagged rows recomputed in EXACT fp32 (per-output ascending-k
//              fmaf, bitwise-identical to proven round-1 path), ILP'd
//   decoder  : bf16 HMMA 2-plane 3-product fused (proven round-7, unchanged)
// ===========================================================================

#define M_ROWS 8192
#define EMB_NUM 1024
#define EMB_DIM 64
#define FLAG_T 1e-8f

typedef unsigned long long u64;
typedef __nv_bfloat16 bf16;
typedef __half f16;

// ---------------------------------------------------------------------------
// Static device scratch (allocation-free rule)
// ---------------------------------------------------------------------------
__device__ f16  g_xh[8192 * 2048];
__device__ f16  g_xm[8192 * 2048];
__device__ f16  g_w0h[1024 * 2048];
__device__ f16  g_w0m[1024 * 2048];
__device__ f16  g_w1h[512 * 1024];
__device__ f16  g_w1m[512 * 1024];
__device__ f16  g_h1h[8192 * 1024];
__device__ f16  g_h1m[8192 * 1024];
__device__ float g_h2[8192 * 512];
__device__ float g_z [8192 * 256];
__device__ float g_cn[EMB_NUM];
__device__ int   g_flags[32768];
__device__ bf16 g_zq[2][8192 * 256];
__device__ bf16 g_d1[2][8192 * 512];
__device__ bf16 g_d2[2][8192 * 1024];
__device__ bf16 g_wd0[2][512 * 256];
__device__ bf16 g_wd1[2][1024 * 512];
__device__ bf16 g_wo[2][2048 * 1024];

// ---------------------------------------------------------------------------
// PTX helpers
// ---------------------------------------------------------------------------
__device__ __forceinline__ uint32_t smem_u32(const void* p) {
    uint32_t a;
    asm("{ .reg .u64 t; cvta.to.shared.u64 t, %1; cvt.u32.u64 %0, t; }" : "=r"(a) : "l"(p));
    return a;
}
__device__ __forceinline__ void cp16(uint32_t dst, const void* src) {
    asm volatile("cp.async.cg.shared.global [%0], [%1], 16;" :: "r"(dst), "l"(src));
}
#define CP_COMMIT() asm volatile("cp.async.commit_group;" ::: "memory")
#define CP_WAIT0()  asm volatile("cp.async.wait_group 0;" ::: "memory")

__device__ __forceinline__ void ldm_x4(uint32_t r[4], uint32_t addr) {
    asm volatile("ldmatrix.sync.aligned.m8n8.x4.shared.b16 {%0,%1,%2,%3}, [%4];"
                 : "=r"(r[0]), "=r"(r[1]), "=r"(r[2]), "=r"(r[3]) : "r"(addr));
}
__device__ __forceinline__ void mma_bf16(float* d, const uint32_t* a, uint32_t b0, uint32_t b1) {
    asm volatile(
        "mma.sync.aligned.m16n8k16.row.col.f32.bf16.bf16.f32 "
        "{%0,%1,%2,%3}, {%4,%5,%6,%7}, {%8,%9}, {%0,%1,%2,%3};"
        : "+f"(d[0]), "+f"(d[1]), "+f"(d[2]), "+f"(d[3])
        : "r"(a[0]), "r"(a[1]), "r"(a[2]), "r"(a[3]), "r"(b0), "r"(b1));
}
__device__ __forceinline__ void mma_f16(float* d, const uint32_t* a, uint32_t b0, uint32_t b1) {
    asm volatile(
        "mma.sync.aligned.m16n8k16.row.col.f32.f16.f16.f32 "
        "{%0,%1,%2,%3}, {%4,%5,%6,%7}, {%8,%9}, {%0,%1,%2,%3};"
        : "+f"(d[0]), "+f"(d[1]), "+f"(d[2]), "+f"(d[3])
        : "r"(a[0]), "r"(a[1]), "r"(a[2]), "r"(a[3]), "r"(b0), "r"(b1));
}
__device__ __forceinline__ u64 pack2f(float lo, float hi) {
    u64 r; asm("mov.b64 %0, {%1, %2};" : "=l"(r) : "f"(lo), "f"(hi)); return r;
}
__device__ __forceinline__ void unpack2f(u64 v, float& lo, float& hi) {
    asm("mov.b64 {%0, %1}, %2;" : "=f"(lo), "=f"(hi) : "l"(v));
}
__device__ __forceinline__ u64 ffma2(u64 a, u64 b, u64 c) {
    u64 d; asm("fma.rn.f32x2 %0, %1, %2, %3;" : "=l"(d) : "l"(a), "l"(b), "l"(c)); return d;
}

// ---------------------------------------------------------------------------
// fp32 tiled SGEMM (exact; used for z layer)
// ---------------------------------------------------------------------------
template <int BM, int BN, int BK, int TM, int TN, bool RELU>
__global__ __launch_bounds__((BM / TM) * (BN / TN))
void gemm_bias_kernel(const float* __restrict__ A,
                      const float* __restrict__ W,
                      const float* __restrict__ bias,
                      float* __restrict__ C,
                      int M, int N, int K) {
    constexpr int THREADS = (BM / TM) * (BN / TN);
    constexpr int PAD = 4;
    __shared__ float As[BK][BM + PAD];
    __shared__ float Ws[BK][BN + PAD];

    const int bm = blockIdx.y * BM;
    const int bn = blockIdx.x * BN;
    const int tid = threadIdx.x;
    const int tx = tid % (BN / TN);
    const int ty = tid / (BN / TN);

    float acc[TM][TN];
#pragma unroll
    for (int i = 0; i < TM; i++)
#pragma unroll
        for (int j = 0; j < TN; j++) acc[i][j] = 0.0f;

    for (int k0 = 0; k0 < K; k0 += BK) {
#pragma unroll
        for (int i = tid; i < BM * BK / 4; i += THREADS) {
            int r  = i / (BK / 4);
            int c4 = i % (BK / 4);
            float4 v = *reinterpret_cast<const float4*>(A + (size_t)(bm + r) * K + k0 + c4 * 4);
            As[c4 * 4 + 0][r] = v.x;
            As[c4 * 4 + 1][r] = v.y;
            As[c4 * 4 + 2][r] = v.z;
            As[c4 * 4 + 3][r] = v.w;
        }
#pragma unroll
        for (int i = tid; i < BN * BK / 4; i += THREADS) {
            int r  = i / (BK / 4);
            int c4 = i % (BK / 4);
            float4 v = *reinterpret_cast<const float4*>(W + (size_t)(bn + r) * K + k0 + c4 * 4);
            Ws[c4 * 4 + 0][r] = v.x;
            Ws[c4 * 4 + 1][r] = v.y;
            Ws[c4 * 4 + 2][r] = v.z;
            Ws[c4 * 4 + 3][r] = v.w;
        }
        __syncthreads();

#pragma unroll
        for (int k = 0; k < BK; k++) {
            float a[TM], b[TN];
            *reinterpret_cast<float4*>(&a[0]) = *reinterpret_cast<const float4*>(&As[k][ty * TM + 0]);
            *reinterpret_cast<float4*>(&a[4]) = *reinterpret_cast<const float4*>(&As[k][ty * TM + 4]);
            *reinterpret_cast<float4*>(&b[0]) = *reinterpret_cast<const float4*>(&Ws[k][tx * TN + 0]);
            *reinterpret_cast<float4*>(&b[4]) = *reinterpret_cast<const float4*>(&Ws[k][tx * TN + 4]);
#pragma unroll
            for (int i = 0; i < TM; i++)
#pragma unroll
                for (int j = 0; j < TN; j++)
                    acc[i][j] = fmaf(a[i], b[j], acc[i][j]);
        }
        __syncthreads();
    }

    float bv[TN];
#pragma unroll
    for (int j = 0; j < TN; j++) bv[j] = bias[bn + tx * TN + j];

#pragma unroll
    for (int i = 0; i < TM; i++) {
        int row = bm + ty * TM + i;
        float out[TN];
#pragma unroll
        for (int j = 0; j < TN; j++) {
            float v = acc[i][j] + bv[j];
            if (RELU) v = fmaxf(v, 0.0f);
            out[j] = v;
        }
        float* cptr = C + (size_t)row * N + bn + tx * TN;
        *reinterpret_cast<float4*>(cptr + 0) = *reinterpret_cast<float4*>(&out[0]);
        *reinterpret_cast<float4*>(cptr + 4) = *reinterpret_cast<float4*>(&out[4]);
    }
}

// ---------------------------------------------------------------------------
// Shared tile geometry for HMMA kernels
// ---------------------------------------------------------------------------
#define DEC_TILE_B  10240
#define DEC_STAGE_B (4 * DEC_TILE_B)
#define DEC_SMEM    (2 * DEC_STAGE_B)

// ---------------------------------------------------------------------------
// ENCODER h1/h2: fp16 2-plane (m-plane pre-scaled x4096), 3 products.
// ---------------------------------------------------------------------------
template <bool RELU, bool OUTPLANES>
__global__ __launch_bounds__(256, 1)
void enc_hmma_kernel(const f16* __restrict__ Ah, const f16* __restrict__ Am,
                     const f16* __restrict__ Bh, const f16* __restrict__ Bm,
                     const float* __restrict__ bias,
                     float* __restrict__ Cf,
                     f16* __restrict__ Ch, f16* __restrict__ Cm,
                     int N, int K) {
    extern __shared__ char dsm[];
    const uint32_t su = smem_u32(dsm);

    const int tid = threadIdx.x;
    const int wid = tid >> 5, lane = tid & 31;
    const int wm = wid >> 2, wn = wid & 3;
    const int bn = blockIdx.x * 128, bm = blockIdx.y * 128;
    const int KC = K >> 5;

    const f16* P[4] = { Ah + (size_t)bm * K, Am + (size_t)bm * K,
                        Bh + (size_t)bn * K, Bm + (size_t)bn * K };

    float accA[4][4][4], accB[4][4][4];
#pragma unroll
    for (int i = 0; i < 4; i++)
#pragma unroll
        for (int j = 0; j < 4; j++)
#pragma unroll
            for (int q = 0; q < 4; q++) { accA[i][j][q] = 0.0f; accB[i][j][q] = 0.0f; }

    auto load_chunk = [&](int stage, int k0) {
#pragma unroll
        for (int t = 0; t < 4; t++) {
            const f16* src = P[t];
#pragma unroll
            for (int j = 0; j < 2; j++) {
                int ch = j * 256 + tid;
                int r = ch >> 2, cc = ch & 3;
                uint32_t off = (uint32_t)((stage * 4 + t) * DEC_TILE_B + r * 80 + cc * 16);
                cp16(su + off, src + (size_t)r * K + k0 + cc * 8);
            }
        }
        CP_COMMIT();
    };

    load_chunk(0, 0);

    const int tA[3] = {0, 0, 1};
    const int tB[3] = {2, 3, 2};

    for (int c = 0; c < KC; c++) {
        CP_WAIT0();
        __syncthreads();
        if (c + 1 < KC) load_chunk((c + 1) & 1, (c + 1) << 5);

        const int stage = c & 1;
#pragma unroll
        for (int p = 0; p < 3; p++) {
            const uint32_t baseA = su + (uint32_t)((stage * 4 + tA[p]) * DEC_TILE_B);
            const uint32_t baseB = su + (uint32_t)((stage * 4 + tB[p]) * DEC_TILE_B);
            float (*acc)[4][4] = (p == 0) ? accA : accB;
#pragma unroll
            for (int ks = 0; ks < 2; ks++) {
                uint32_t af[4][4], bg[2][4];
#pragma unroll
                for (int mt = 0; mt < 4; mt++) {
                    uint32_t addr = baseA + (uint32_t)((wm * 64 + mt * 16 + ((lane >> 3) & 1) * 8 + (lane & 7)) * 80
                                                       + (ks * 16 + (lane >> 4) * 8) * 2);
                    ldm_x4(af[mt], addr);
                }
#pragma unroll
                for (int np = 0; np < 2; np++) {
                    uint32_t addr = baseB + (uint32_t)((wn * 32 + np * 16 + ((lane >> 4) & 1) * 8 + (lane & 7)) * 80
                                                       + (ks * 16 + ((lane >> 3) & 1) * 8) * 2);
                    ldm_x4(bg[np], addr);
                }
#pragma unroll
                for (int mt = 0; mt < 4; mt++)
#pragma unroll
                    for (int nt = 0; nt < 4; nt++)
                        mma_f16(acc[mt][nt], af[mt], bg[nt >> 1][(nt & 1) * 2], bg[nt >> 1][(nt & 1) * 2 + 1]);
            }
        }
        __syncthreads();
    }

    const float SINV = 1.0f / 4096.0f;
#pragma unroll
    for (int mt = 0; mt < 4; mt++) {
#pragma unroll
        for (int nt = 0; nt < 4; nt++) {
            const int r0 = bm + wm * 64 + mt * 16 + (lane >> 2);
            const int c0 = bn + wn * 32 + nt * 8 + (lane & 3) * 2;
            const float bv0 = bias[c0], bv1 = bias[c0 + 1];
#pragma unroll
            for (int h = 0; h < 2; h++) {
                const int r = r0 + h * 8;
                float v0 = fmaf(accB[mt][nt][h * 2 + 0], SINV, accA[mt][nt][h * 2 + 0]) + bv0;
                float v1 = fmaf(accB[mt][nt][h * 2 + 1], SINV, accA[mt][nt][h * 2 + 1]) + bv1;
                if (RELU) { v0 = fmaxf(v0, 0.0f); v1 = fmaxf(v1, 0.0f); }
                const size_t o = (size_t)r * N + c0;
                if (!OUTPLANES) {
                    *reinterpret_cast<float2*>(Cf + o) = make_float2(v0, v1);
                } else {
                    f16 h0 = __float2half_rn(v0), h1v = __float2half_rn(v1);
                    float r0f = (v0 - __half2float(h0)) * 4096.0f;
                    float r1f = (v1 - __half2float(h1v)) * 4096.0f;
                    __half2 hp; hp.x = h0; hp.y = h1v;
                    __half2 mp; mp.x = __float2half_rn(r0f); mp.y = __float2half_rn(r1f);
                    *reinterpret_cast<__half2*>(Ch + o) = hp;
                    *reinterpret_cast<__half2*>(Cm + o) = mp;
                }
            }
        }
    }
}

// ---------------------------------------------------------------------------
// DECODER: bf16 HMMA, 2-plane, 3-product fused (byte-identical to round 7)
// ---------------------------------------------------------------------------
template <bool RELU, int OUTP>
__global__ __launch_bounds__(256, 2)
void gemm_hmma_kernel(const bf16* __restrict__ A0, const bf16* __restrict__ A1,
                      const bf16* __restrict__ B0, const bf16* __restrict__ B1,
                      const float* __restrict__ bias,
                      float* __restrict__ Cf,
                      bf16* __restrict__ Ch, bf16* __restrict__ Cm,
                      int N, int K) {
    extern __shared__ char dsm[];
    const uint32_t su = smem_u32(dsm);

    const int tid = threadIdx.x;
    const int wid = tid >> 5, lane = tid & 31;
    const int wm = wid >> 2, wn = wid & 3;
    const int bn = blockIdx.x * 128, bm = blockIdx.y * 128;
    const int KC = K >> 5;

    const bf16* P[4] = { A0 + (size_t)bm * K, A1 + (size_t)bm * K,
                         B0 + (size_t)bn * K, B1 + (size_t)bn * K };

    float acc[4][4][4];
#pragma unroll
    for (int i = 0; i < 4; i++)
#pragma unroll
        for (int j = 0; j < 4; j++)
#pragma unroll
            for (int q = 0; q < 4; q++) acc[i][j][q] = 0.0f;

    auto load_chunk = [&](int stage, int k0) {
#pragma unroll
        for (int t = 0; t < 4; t++) {
            const bf16* src = P[t];
#pragma unroll
            for (int j = 0; j < 2; j++) {
                int ch = j * 256 + tid;
                int r = ch >> 2, cc = ch & 3;
                uint32_t off = (uint32_t)((stage * 4 + t) * DEC_TILE_B + r * 80 + cc * 16);
                cp16(su + off, src + (size_t)r * K + k0 + cc * 8);
            }
        }
        CP_COMMIT();
    };

    load_chunk(0, 0);

    const int tA[3] = {0, 0, 1};
    const int tB[3] = {2, 3, 2};

    for (int c = 0; c < KC; c++) {
        CP_WAIT0();
        __syncthreads();
        if (c + 1 < KC) load_chunk((c + 1) & 1, (c + 1) << 5);

        const int stage = c & 1;
#pragma unroll
        for (int p = 0; p < 3; p++) {
            const uint32_t baseA = su + (uint32_t)((stage * 4 + tA[p]) * DEC_TILE_B);
            const uint32_t baseB = su + (uint32_t)((stage * 4 + tB[p]) * DEC_TILE_B);
#pragma unroll
            for (int ks = 0; ks < 2; ks++) {
                uint32_t af[4][4], bg[2][4];
#pragma unroll
                for (int mt = 0; mt < 4; mt++) {
                    uint32_t addr = baseA + (uint32_t)((wm * 64 + mt * 16 + ((lane >> 3) & 1) * 8 + (lane & 7)) * 80
                                                       + (ks * 16 + (lane >> 4) * 8) * 2);
                    ldm_x4(af[mt], addr);
                }
#pragma unroll
                for (int np = 0; np < 2; np++) {
                    uint32_t addr = baseB + (uint32_t)((wn * 32 + np * 16 + ((lane >> 4) & 1) * 8 + (lane & 7)) * 80
                                                       + (ks * 16 + ((lane >> 3) & 1) * 8) * 2);
                    ldm_x4(bg[np], addr);
                }
#pragma unroll
                for (int mt = 0; mt < 4; mt++)
#pragma unroll
                    for (int nt = 0; nt < 4; nt++)
                        mma_bf16(acc[mt][nt], af[mt], bg[nt >> 1][(nt & 1) * 2], bg[nt >> 1][(nt & 1) * 2 + 1]);
            }
        }
        __syncthreads();
    }

#pragma unroll
    for (int mt = 0; mt < 4; mt++) {
#pragma unroll
        for (int nt = 0; nt < 4; nt++) {
            const int r0 = bm + wm * 64 + mt * 16 + (lane >> 2);
            const int c0 = bn + wn * 32 + nt * 8 + (lane & 3) * 2;
            const float bv0 = bias[c0], bv1 = bias[c0 + 1];
#pragma unroll
            for (int h = 0; h < 2; h++) {
                const int r = r0 + h * 8;
                float v0 = acc[mt][nt][h * 2 + 0] + bv0;
                float v1 = acc[mt][nt][h * 2 + 1] + bv1;
                if (RELU) { v0 = fmaxf(v0, 0.0f); v1 = fmaxf(v1, 0.0f); }
                const size_t o = (size_t)r * N + c0;
                if (OUTP == 0) {
                    *reinterpret_cast<float2*>(Cf + o) = make_float2(v0, v1);
                } else {
                    bf16 h0 = __float2bfloat16(v0), h1v = __float2bfloat16(v1);
                    float r0f = v0 - __bfloat162float(h0);
                    float r1f = v1 - __bfloat162float(h1v);
                    __nv_bfloat162 hp; hp.x = h0; hp.y = h1v;
                    __nv_bfloat162 mp; mp.x = __float2bfloat16(r0f); mp.y = __float2bfloat16(r1f);
                    *reinterpret_cast<__nv_bfloat162*>(Ch + o) = hp;
                    *reinterpret_cast<__nv_bfloat162*>(Cm + o) = mp;
                }
            }
        }
    }
}

// ---------------------------------------------------------------------------
// Splits
// ---------------------------------------------------------------------------
__global__ void split2h_kernel(const float* __restrict__ src,
                               f16* __restrict__ h, f16* __restrict__ m, int n) {
    int i = blockIdx.x * blockDim.x + threadIdx.x;
    if (i < n) {
        float v = src[i];
        f16 a = __float2half_rn(v);
        float r1 = (v - __half2float(a)) * 4096.0f;
        h[i] = a; m[i] = __float2half_rn(r1);
    }
}
__global__ void split2_kernel(const float* __restrict__ src,
                              bf16* __restrict__ h, bf16* __restrict__ m, int n) {
    int i = blockIdx.x * blockDim.x + threadIdx.x;
    if (i < n) {
        float v = src[i];
        bf16 a = __float2bfloat16(v);
        float r1 = v - __bfloat162float(a);
        h[i] = a; m[i] = __float2bfloat16(r1);
    }
}

// ---------------------------------------------------------------------------
// Codebook squared norms
// ---------------------------------------------------------------------------
__global__ void cnorm_kernel(const float* __restrict__ cb, float* __restrict__ cn) {
    int i = blockIdx.x * blockDim.x + threadIdx.x;
    if (i >= EMB_NUM) return;
    const float4* p = reinterpret_cast<const float4*>(cb + (size_t)i * EMB_DIM);
    float s = 0.0f;
#pragma unroll
    for (int d = 0; d < EMB_DIM / 4; d++) {
        float4 v = p[d];
        s += v.x * v.x + v.y * v.y + v.z * v.z + v.w * v.w;
    }
    cn[i] = s;
}

// ---------------------------------------------------------------------------
// VQ with gap test: fp32 distances from TC z; flag groups with tiny gaps.
// ---------------------------------------------------------------------------
__global__ __launch_bounds__(256)
void vq_kernel(const float* __restrict__ z,
               const float* __restrict__ cb,
               const float* __restrict__ cn,
               bf16* __restrict__ qh, bf16* __restrict__ qm,
               int* __restrict__ flags) {
    constexpr int CHUNK = 128;
    __shared__ float sc[CHUNK][EMB_DIM];
    __shared__ float scn[CHUNK];

    const int row = blockIdx.x * blockDim.x + threadIdx.x;
    const float* zp = z + (size_t)row * EMB_DIM;

    u64 m2zP[EMB_DIM / 2];
#pragma unroll
    for (int d = 0; d < EMB_DIM / 4; d++) {
        float4 v = reinterpret_cast<const float4*>(zp)[d];
        m2zP[d * 2 + 0] = pack2f(-2.0f * v.x, -2.0f * v.y);
        m2zP[d * 2 + 1] = pack2f(-2.0f * v.z, -2.0f * v.w);
    }

    float best = 3.0e38f, best2 = 3.0e38f;
    int bidx = 0;
    for (int ch = 0; ch < EMB_NUM / CHUNK; ch++) {
        __syncthreads();
        const float4* src = reinterpret_cast<const float4*>(cb + (size_t)ch * CHUNK * EMB_DIM);
        float4* dst = reinterpret_cast<float4*>(&sc[0][0]);
        for (int i = threadIdx.x; i < CHUNK * EMB_DIM / 4; i += 256) dst[i] = src[i];
        if (threadIdx.x < CHUNK) scn[threadIdx.x] = cn[ch * CHUNK + threadIdx.x];
        __syncthreads();

        for (int j = 0; j < CHUNK; j++) {
            u64 sP = 0ull;
#pragma unroll
            for (int d = 0; d < EMB_DIM / 4; d++) {
                float4 cc = reinterpret_cast<const float4*>(&sc[j][0])[d];
                sP = ffma2(pack2f(cc.x, cc.y), m2zP[d * 2 + 0], sP);
                sP = ffma2(pack2f(cc.z, cc.w), m2zP[d * 2 + 1], sP);
            }
            float lo, hi;
            unpack2f(sP, lo, hi);
            float s = scn[j] + lo + hi;
            if (s < best) { best2 = best; best = s; bidx = ch * CHUNK + j; }
            else if (s < best2) { best2 = s; }
        }
    }

    flags[row] = (best2 - best < FLAG_T) ? 1 : 0;

    const float* cp = cb + (size_t)bidx * EMB_DIM;
#pragma unroll
    for (int d = 0; d < EMB_DIM; d++) {
        float zz = zp[d];
        float v = zz + (cp[d] - zz);
        bf16 a = __float2bfloat16(v);
        float r1 = v - __bfloat162float(a);
        size_t o = (size_t)row * EMB_DIM + d;
        qh[o] = a; qm[o] = __float2bfloat16(r1);
    }
}

// ---------------------------------------------------------------------------
// REPAIR: for flagged x-rows, recompute h1/h2/z with per-output ascending-k
// fp32 fmaf chains (bitwise-identical per output to the proven fp32 path),
// 4 independent chains per thread for ILP; redo argmin exactly; overwrite zq.
// ---------------------------------------------------------------------------
__global__ __launch_bounds__(256)
void repair_kernel(const float* __restrict__ x,
                   const float* __restrict__ w0, const float* __restrict__ b0,
                   const float* __restrict__ w1, const float* __restrict__ b1,
                   const float* __restrict__ zw, const float* __restrict__ zb,
                   const float* __restrict__ cb, const float* __restrict__ cn,
                   const int* __restrict__ flags,
                   bf16* __restrict__ qh, bf16* __restrict__ qm) {
    const int row = blockIdx.x;
    const int f0 = flags[row * 4 + 0], f1 = flags[row * 4 + 1];
    const int f2 = flags[row * 4 + 2], f3 = flags[row * 4 + 3];
    if (!(f0 | f1 | f2 | f3)) return;

    __shared__ float xs[2048];
    __shared__ float h1s[1024];
    __shared__ float h2s[512];
    __shared__ float zs[256];
    __shared__ float rbest[256];
    __shared__ int ridx[256];

    const int t = threadIdx.x;

    // stage x row in smem
    {
        const float4* xr = reinterpret_cast<const float4*>(x + (size_t)row * 2048);
        float4* xd = reinterpret_cast<float4*>(xs);
        for (int i = t; i < 512; i += 256) xd[i] = xr[i];
    }
    __syncthreads();

    // exact h1: 4 outputs/thread, independent ascending-k chains (ILP=4)
    {
        const float* r0 = w0 + (size_t)(t      ) * 2048;
        const float* r1 = w0 + (size_t)(t + 256) * 2048;
        const float* r2 = w0 + (size_t)(t + 512) * 2048;
        const float* r3 = w0 + (size_t)(t + 768) * 2048;
        float a0 = 0.0f, a1 = 0.0f, a2 = 0.0f, a3 = 0.0f;
        for (int k = 0; k < 2048; k += 4) {
            float4 xv = *reinterpret_cast<const float4*>(xs + k);
            float4 v0 = *reinterpret_cast<const float4*>(r0 + k);
            float4 v1 = *reinterpret_cast<const float4*>(r1 + k);
            float4 v2 = *reinterpret_cast<const float4*>(r2 + k);
            float4 v3 = *reinterpret_cast<const float4*>(r3 + k);
            a0 = fmaf(xv.x, v0.x, a0); a0 = fmaf(xv.y, v0.y, a0);
            a0 = fmaf(xv.z, v0.z, a0); a0 = fmaf(xv.w, v0.w, a0);
            a1 = fmaf(xv.x, v1.x, a1); a1 = fmaf(xv.y, v1.y, a1);
            a1 = fmaf(xv.z, v1.z, a1); a1 = fmaf(xv.w, v1.w, a1);
            a2 = fmaf(xv.x, v2.x, a2); a2 = fmaf(xv.y, v2.y, a2);
            a2 = fmaf(xv.z, v2.z, a2); a2 = fmaf(xv.w, v2.w, a2);
            a3 = fmaf(xv.x, v3.x, a3); a3 = fmaf(xv.y, v3.y, a3);
            a3 = fmaf(xv.z, v3.z, a3); a3 = fmaf(xv.w, v3.w, a3);
        }
        h1s[t      ] = fmaxf(a0 + b0[t      ], 0.0f);
        h1s[t + 256] = fmaxf(a1 + b0[t + 256], 0.0f);
        h1s[t + 512] = fmaxf(a2 + b0[t + 512], 0.0f);
        h1s[t + 768] = fmaxf(a3 + b0[t + 768], 0.0f);
    }
    __syncthreads();

    // exact h2: 2 outputs/thread
    {
        const float* r0 = w1 + (size_t)(t      ) * 1024;
        const float* r1 = w1 + (size_t)(t + 256) * 1024;
        float a0 = 0.0f, a1 = 0.0f;
        for (int k = 0; k < 1024; k += 4) {
            float4 hv = *reinterpret_cast<const float4*>(h1s + k);
            float4 v0 = *reinterpret_cast<const float4*>(r0 + k);
            float4 v1 = *reinterpret_cast<const float4*>(r1 + k);
            a0 = fmaf(hv.x, v0.x, a0); a0 = fmaf(hv.y, v0.y, a0);
            a0 = fmaf(hv.z, v0.z, a0); a0 = fmaf(hv.w, v0.w, a0);
            a1 = fmaf(hv.x, v1.x, a1); a1 = fmaf(hv.y, v1.y, a1);
            a1 = fmaf(hv.z, v1.z, a1); a1 = fmaf(hv.w, v1.w, a1);
        }
        h2s[t      ] = fmaxf(a0 + b1[t      ], 0.0f);
        h2s[t + 256] = fmaxf(a1 + b1[t + 256], 0.0f);
    }
    __syncthreads();

    // exact z: 1 output/thread (first 256 threads)
    {
        const float* wr = zw + (size_t)t * 512;
        float acc = 0.0f;
        for (int k = 0; k < 512; k += 4) {
            float4 hv = *reinterpret_cast<const float4*>(h2s + k);
            float4 wv = *reinterpret_cast<const float4*>(wr + k);
            acc = fmaf(hv.x, wv.x, acc); acc = fmaf(hv.y, wv.y, acc);
            acc = fmaf(hv.z, wv.z, acc); acc = fmaf(hv.w, wv.w, acc);
        }
        zs[t] = acc + zb[t];
    }
    __syncthreads();

    const int gf[4] = {f0, f1, f2, f3};
#pragma unroll
    for (int g = 0; g < 4; g++) {
        if (!gf[g]) continue;
        const float* zg = zs + g * EMB_DIM;
        u64 m2zP[EMB_DIM / 2];
#pragma unroll
        for (int d = 0; d < EMB_DIM / 4; d++) {
            float4 v = *reinterpret_cast<const float4*>(zg + d * 4);
            m2zP[d * 2 + 0] = pack2f(-2.0f * v.x, -2.0f * v.y);
            m2zP[d * 2 + 1] = pack2f(-2.0f * v.z, -2.0f * v.w);
        }
        float best = 3.0e38f;
        int bidx = 0;
        for (int jj = 0; jj < 4; jj++) {
            int j = jj * 256 + t;
            u64 sP = 0ull;
            const float4* cc4 = reinterpret_cast<const float4*>(cb + (size_t)j * EMB_DIM);
#pragma unroll
            for (int d = 0; d < EMB_DIM / 4; d++) {
                float4 cc = cc4[d];
                sP = ffma2(pack2f(cc.x, cc.y), m2zP[d * 2 + 0], sP);
                sP = ffma2(pack2f(cc.z, cc.w), m2zP[d * 2 + 1], sP);
            }
            float lo, hi;
            unpack2f(sP, lo, hi);
            float s = cn[j] + lo + hi;
            if (s < best || (s == best && j < bidx)) { best = s; bidx = j; }
        }
        rbest[t] = best; ridx[t] = bidx;
        __syncthreads();
        for (int s2 = 128; s2 > 0; s2 >>= 1) {
            if (t < s2) {
                float ob = rbest[t + s2]; int oi = ridx[t + s2];
                if (ob < rbest[t] || (ob == rbest[t] && oi < ridx[t])) { rbest[t] = ob; ridx[t] = oi; }
            }
            __syncthreads();
        }
        const int fin = ridx[0];
        if (t < EMB_DIM) {
            float zz = zg[t];
            float v = zz + (cb[(size_t)fin * EMB_DIM + t] - zz);
            bf16 a = __float2bfloat16(v);
            float r1 = v - __bfloat162float(a);
            size_t o = ((size_t)row * 4 + g) * EMB_DIM + t;
            qh[o] = a; qm[o] = __float2bfloat16(r1);
        }
        __syncthreads();
    }
}

// ---------------------------------------------------------------------------
// Host launch
// ---------------------------------------------------------------------------
template <bool RELU, bool OUTPLANES>
static inline void launch_encH(const f16* Ah, const f16* Am,
                               const f16* Bh, const f16* Bm,
                               const float* bias, float* Cf, f16* Ch, f16* Cm,
                               int N, int K) {
    cudaFuncSetAttribute(enc_hmma_kernel<RELU, OUTPLANES>,
                         cudaFuncAttributeMaxDynamicSharedMemorySize, DEC_SMEM);
    dim3 grid(N / 128, M_ROWS / 128);
    enc_hmma_kernel<RELU, OUTPLANES><<<grid, 256, DEC_SMEM>>>(Ah, Am, Bh, Bm, bias, Cf, Ch, Cm, N, K);
}

template <bool RELU, int OUTP>
static inline void launch_dec(const bf16* A0, const bf16* A1,
                              const bf16* B0, const bf16* B1,
                              const float* bias, float* Cf, bf16* Ch, bf16* Cm,
                              int N, int K) {
    cudaFuncSetAttribute(gemm_hmma_kernel<RELU, OUTP>,
                         cudaFuncAttributeMaxDynamicSharedMemorySize, DEC_SMEM);
    dim3 grid(N / 128, M_ROWS / 128);
    gemm_hmma_kernel<RELU, OUTP><<<grid, 256, DEC_SMEM>>>(A0, A1, B0, B1, bias, Cf, Ch, Cm, N, K);
}

extern "C" void kernel_launch(void* const* d_in, const int* in_sizes, int n_in,
                              void* d_out, int out_size) {
    const float* x        = (const float*)d_in[0];
    const float* enc0_w   = (const float*)d_in[1];
    const float* enc0_b   = (const float*)d_in[2];
    const float* enc1_w   = (const float*)d_in[3];
    const float* enc1_b   = (const float*)d_in[4];
    const float* z_w      = (const float*)d_in[5];
    const float* z_b      = (const float*)d_in[6];
    const float* codebook = (const float*)d_in[7];
    const float* dec0_w   = (const float*)d_in[8];
    const float* dec0_b   = (const float*)d_in[9];
    const float* dec1_w   = (const float*)d_in[10];
    const float* dec1_b   = (const float*)d_in[11];
    const float* out_w    = (const float*)d_in[12];
    const float* out_b    = (const float*)d_in[13];
    float* out = (float*)d_out;

    f16 *xh, *xm, *w0h, *w0m, *w1h, *w1m, *h1h, *h1m;
    cudaGetSymbolAddress((void**)&xh, g_xh);
    cudaGetSymbolAddress((void**)&xm, g_xm);
    cudaGetSymbolAddress((void**)&w0h, g_w0h);
    cudaGetSymbolAddress((void**)&w0m, g_w0m);
    cudaGetSymbolAddress((void**)&w1h, g_w1h);
    cudaGetSymbolAddress((void**)&w1m, g_w1m);
    cudaGetSymbolAddress((void**)&h1h, g_h1h);
    cudaGetSymbolAddress((void**)&h1m, g_h1m);
    float *h2, *z, *cn;
    int* flags;
    cudaGetSymbolAddress((void**)&h2, g_h2);
    cudaGetSymbolAddress((void**)&z,  g_z);
    cudaGetSymbolAddress((void**)&cn, g_cn);
    cudaGetSymbolAddress((void**)&flags, g_flags);
    bf16 (*zq)[8192 * 256];   cudaGetSymbolAddress((void**)&zq, g_zq);
    bf16 (*d1)[8192 * 512];   cudaGetSymbolAddress((void**)&d1, g_d1);
    bf16 (*d2)[8192 * 1024];  cudaGetSymbolAddress((void**)&d2, g_d2);
    bf16 (*wd0)[512 * 256];   cudaGetSymbolAddress((void**)&wd0, g_wd0);
    bf16 (*wd1)[1024 * 512];  cudaGetSymbolAddress((void**)&wd1, g_wd1);
    bf16 (*wo)[2048 * 1024];  cudaGetSymbolAddress((void**)&wo, g_wo);

    // splits
    split2h_kernel<<<(8192 * 2048 + 255) / 256, 256>>>(x, xh, xm, 8192 * 2048);
    split2h_kernel<<<(1024 * 2048 + 255) / 256, 256>>>(enc0_w, w0h, w0m, 1024 * 2048);
    split2h_kernel<<<(512 * 1024 + 255) / 256, 256>>>(enc1_w, w1h, w1m, 512 * 1024);
    split2_kernel<<<(512 * 256 + 255) / 256, 256>>>(dec0_w, wd0[0], wd0[1], 512 * 256);
    split2_kernel<<<(1024 * 512 + 255) / 256, 256>>>(dec1_w, wd1[0], wd1[1], 1024 * 512);
    split2_kernel<<<(2048 * 1024 + 255) / 256, 256>>>(out_w, wo[0], wo[1], 2048 * 1024);

    // encoder: h1, h2 via fp16 HMMA; z fp32 from h2
    launch_encH<true, true >(xh, xm, w0h, w0m, enc0_b, nullptr, h1h, h1m, 1024, 2048);
    launch_encH<true, false>(h1h, h1m, w1h, w1m, enc1_b, h2, nullptr, nullptr, 512, 1024);
    {
        dim3 grid(256 / 128, M_ROWS / 128);
        gemm_bias_kernel<128, 128, 16, 8, 8, false><<<grid, 256>>>(h2, z_w, z_b, z, M_ROWS, 256, 512);
    }

    // vector quantization with gap test, then exact repair of flagged rows
    cnorm_kernel<<<4, 256>>>(codebook, cn);
    vq_kernel<<<(M_ROWS * 256 / EMB_DIM) / 256, 256>>>(z, codebook, cn, zq[0], zq[1], flags);
    repair_kernel<<<M_ROWS, 256>>>(x, enc0_w, enc0_b, enc1_w, enc1_b, z_w, z_b,
                                   codebook, cn, flags, zq[0], zq[1]);

    // decoder (unchanged)
    launch_dec<true,  2>(zq[0], zq[1], wd0[0], wd0[1], dec0_b, nullptr, d1[0], d1[1], 512, 256);
    launch_dec<true,  2>(d1[0], d1[1], wd1[0], wd1[1], dec1_b, nullptr, d2[0], d2[1], 1024, 512);
    launch_dec<false, 0>(d2[0], d2[1], wo[0], wo[1],  out_b,  out, nullptr, nullptr, 2048, 1024);
}

// round 11
// speedup vs baseline: 2.6916x; 1.0470x over previous
#include <cuda_runtime.h>
#include <cuda_bf16.h>
#include <cuda_fp16.h>
#include <cstdint>

// ===========================================================================
// VQ-VAE forward on GB300:
//   encoder  : fp16 2-plane HMMA, UNSCALED residuals, merged accumulator
//              (2 CTAs/SM), 3 products hh+hm+mh
//   VQ       : fp32 distances from TC z + best2 gap test -> flags (T=1e-8)
//   repair   : flagged rows recomputed in EXACT fp32 (proven round-10 path)
//   decoder  : bf16 HMMA 2-plane 3-product fused (proven, unchanged)
// ===========================================================================

#define M_ROWS 8192
#define EMB_NUM 1024
#define EMB_DIM 64
#define FLAG_T 1e-8f

typedef unsigned long long u64;
typedef __nv_bfloat16 bf16;
typedef __half f16;

// ---------------------------------------------------------------------------
// Static device scratch (allocation-free rule)
// ---------------------------------------------------------------------------
__device__ f16  g_xh[8192 * 2048];
__device__ f16  g_xm[8192 * 2048];
__device__ f16  g_w0h[1024 * 2048];
__device__ f16  g_w0m[1024 * 2048];
__device__ f16  g_w1h[512 * 1024];
__device__ f16  g_w1m[512 * 1024];
__device__ f16  g_h1h[8192 * 1024];
__device__ f16  g_h1m[8192 * 1024];
__device__ float g_h2[8192 * 512];
__device__ float g_z [8192 * 256];
__device__ float g_cn[EMB_NUM];
__device__ int   g_flags[32768];
__device__ bf16 g_zq[2][8192 * 256];
__device__ bf16 g_d1[2][8192 * 512];
__device__ bf16 g_d2[2][8192 * 1024];
__device__ bf16 g_wd0[2][512 * 256];
__device__ bf16 g_wd1[2][1024 * 512];
__device__ bf16 g_wo[2][2048 * 1024];

// ---------------------------------------------------------------------------
// PTX helpers
// ---------------------------------------------------------------------------
__device__ __forceinline__ uint32_t smem_u32(const void* p) {
    uint32_t a;
    asm("{ .reg .u64 t; cvta.to.shared.u64 t, %1; cvt.u32.u64 %0, t; }" : "=r"(a) : "l"(p));
    return a;
}
__device__ __forceinline__ void cp16(uint32_t dst, const void* src) {
    asm volatile("cp.async.cg.shared.global [%0], [%1], 16;" :: "r"(dst), "l"(src));
}
#define CP_COMMIT() asm volatile("cp.async.commit_group;" ::: "memory")
#define CP_WAIT0()  asm volatile("cp.async.wait_group 0;" ::: "memory")

__device__ __forceinline__ void ldm_x4(uint32_t r[4], uint32_t addr) {
    asm volatile("ldmatrix.sync.aligned.m8n8.x4.shared.b16 {%0,%1,%2,%3}, [%4];"
                 : "=r"(r[0]), "=r"(r[1]), "=r"(r[2]), "=r"(r[3]) : "r"(addr));
}
__device__ __forceinline__ void mma_bf16(float* d, const uint32_t* a, uint32_t b0, uint32_t b1) {
    asm volatile(
        "mma.sync.aligned.m16n8k16.row.col.f32.bf16.bf16.f32 "
        "{%0,%1,%2,%3}, {%4,%5,%6,%7}, {%8,%9}, {%0,%1,%2,%3};"
        : "+f"(d[0]), "+f"(d[1]), "+f"(d[2]), "+f"(d[3])
        : "r"(a[0]), "r"(a[1]), "r"(a[2]), "r"(a[3]), "r"(b0), "r"(b1));
}
__device__ __forceinline__ void mma_f16(float* d, const uint32_t* a, uint32_t b0, uint32_t b1) {
    asm volatile(
        "mma.sync.aligned.m16n8k16.row.col.f32.f16.f16.f32 "
        "{%0,%1,%2,%3}, {%4,%5,%6,%7}, {%8,%9}, {%0,%1,%2,%3};"
        : "+f"(d[0]), "+f"(d[1]), "+f"(d[2]), "+f"(d[3])
        : "r"(a[0]), "r"(a[1]), "r"(a[2]), "r"(a[3]), "r"(b0), "r"(b1));
}
__device__ __forceinline__ u64 pack2f(float lo, float hi) {
    u64 r; asm("mov.b64 %0, {%1, %2};" : "=l"(r) : "f"(lo), "f"(hi)); return r;
}
__device__ __forceinline__ void unpack2f(u64 v, float& lo, float& hi) {
    asm("mov.b64 {%0, %1}, %2;" : "=f"(lo), "=f"(hi) : "l"(v));
}
__device__ __forceinline__ u64 ffma2(u64 a, u64 b, u64 c) {
    u64 d; asm("fma.rn.f32x2 %0, %1, %2, %3;" : "=l"(d) : "l"(a), "l"(b), "l"(c)); return d;
}

// ---------------------------------------------------------------------------
// fp32 tiled SGEMM (exact; used for z layer)
// ---------------------------------------------------------------------------
template <int BM, int BN, int BK, int TM, int TN, bool RELU>
__global__ __launch_bounds__((BM / TM) * (BN / TN))
void gemm_bias_kernel(const float* __restrict__ A,
                      const float* __restrict__ W,
                      const float* __restrict__ bias,
                      float* __restrict__ C,
                      int M, int N, int K) {
    constexpr int THREADS = (BM / TM) * (BN / TN);
    constexpr int PAD = 4;
    __shared__ float As[BK][BM + PAD];
    __shared__ float Ws[BK][BN + PAD];

    const int bm = blockIdx.y * BM;
    const int bn = blockIdx.x * BN;
    const int tid = threadIdx.x;
    const int tx = tid % (BN / TN);
    const int ty = tid / (BN / TN);

    float acc[TM][TN];
#pragma unroll
    for (int i = 0; i < TM; i++)
#pragma unroll
        for (int j = 0; j < TN; j++) acc[i][j] = 0.0f;

    for (int k0 = 0; k0 < K; k0 += BK) {
#pragma unroll
        for (int i = tid; i < BM * BK / 4; i += THREADS) {
            int r  = i / (BK / 4);
            int c4 = i % (BK / 4);
            float4 v = *reinterpret_cast<const float4*>(A + (size_t)(bm + r) * K + k0 + c4 * 4);
            As[c4 * 4 + 0][r] = v.x;
            As[c4 * 4 + 1][r] = v.y;
            As[c4 * 4 + 2][r] = v.z;
            As[c4 * 4 + 3][r] = v.w;
        }
#pragma unroll
        for (int i = tid; i < BN * BK / 4; i += THREADS) {
            int r  = i / (BK / 4);
            int c4 = i % (BK / 4);
            float4 v = *reinterpret_cast<const float4*>(W + (size_t)(bn + r) * K + k0 + c4 * 4);
            Ws[c4 * 4 + 0][r] = v.x;
            Ws[c4 * 4 + 1][r] = v.y;
            Ws[c4 * 4 + 2][r] = v.z;
            Ws[c4 * 4 + 3][r] = v.w;
        }
        __syncthreads();

#pragma unroll
        for (int k = 0; k < BK; k++) {
            float a[TM], b[TN];
            *reinterpret_cast<float4*>(&a[0]) = *reinterpret_cast<const float4*>(&As[k][ty * TM + 0]);
            *reinterpret_cast<float4*>(&a[4]) = *reinterpret_cast<const float4*>(&As[k][ty * TM + 4]);
            *reinterpret_cast<float4*>(&b[0]) = *reinterpret_cast<const float4*>(&Ws[k][tx * TN + 0]);
            *reinterpret_cast<float4*>(&b[4]) = *reinterpret_cast<const float4*>(&Ws[k][tx * TN + 4]);
#pragma unroll
            for (int i = 0; i < TM; i++)
#pragma unroll
                for (int j = 0; j < TN; j++)
                    acc[i][j] = fmaf(a[i], b[j], acc[i][j]);
        }
        __syncthreads();
    }

    float bv[TN];
#pragma unroll
    for (int j = 0; j < TN; j++) bv[j] = bias[bn + tx * TN + j];

#pragma unroll
    for (int i = 0; i < TM; i++) {
        int row = bm + ty * TM + i;
        float out[TN];
#pragma unroll
        for (int j = 0; j < TN; j++) {
            float v = acc[i][j] + bv[j];
            if (RELU) v = fmaxf(v, 0.0f);
            out[j] = v;
        }
        float* cptr = C + (size_t)row * N + bn + tx * TN;
        *reinterpret_cast<float4*>(cptr + 0) = *reinterpret_cast<float4*>(&out[0]);
        *reinterpret_cast<float4*>(cptr + 4) = *reinterpret_cast<float4*>(&out[4]);
    }
}

// ---------------------------------------------------------------------------
// Shared tile geometry for HMMA kernels
// ---------------------------------------------------------------------------
#define DEC_TILE_B  10240
#define DEC_STAGE_B (4 * DEC_TILE_B)
#define DEC_SMEM    (2 * DEC_STAGE_B)

// ---------------------------------------------------------------------------
// ENCODER h1/h2: fp16 2-plane, UNSCALED residuals, MERGED accumulator.
// 3 products (hh, hm, mh) into one acc -> decoder-size regs -> 2 CTAs/SM.
// ---------------------------------------------------------------------------
template <bool RELU, bool OUTPLANES>
__global__ __launch_bounds__(256, 2)
void enc_hmma_kernel(const f16* __restrict__ Ah, const f16* __restrict__ Am,
                     const f16* __restrict__ Bh, const f16* __restrict__ Bm,
                     const float* __restrict__ bias,
                     float* __restrict__ Cf,
                     f16* __restrict__ Ch, f16* __restrict__ Cm,
                     int N, int K) {
    extern __shared__ char dsm[];
    const uint32_t su = smem_u32(dsm);

    const int tid = threadIdx.x;
    const int wid = tid >> 5, lane = tid & 31;
    const int wm = wid >> 2, wn = wid & 3;
    const int bn = blockIdx.x * 128, bm = blockIdx.y * 128;
    const int KC = K >> 5;

    const f16* P[4] = { Ah + (size_t)bm * K, Am + (size_t)bm * K,
                        Bh + (size_t)bn * K, Bm + (size_t)bn * K };

    float acc[4][4][4];
#pragma unroll
    for (int i = 0; i < 4; i++)
#pragma unroll
        for (int j = 0; j < 4; j++)
#pragma unroll
            for (int q = 0; q < 4; q++) acc[i][j][q] = 0.0f;

    auto load_chunk = [&](int stage, int k0) {
#pragma unroll
        for (int t = 0; t < 4; t++) {
            const f16* src = P[t];
#pragma unroll
            for (int j = 0; j < 2; j++) {
                int ch = j * 256 + tid;
                int r = ch >> 2, cc = ch & 3;
                uint32_t off = (uint32_t)((stage * 4 + t) * DEC_TILE_B + r * 80 + cc * 16);
                cp16(su + off, src + (size_t)r * K + k0 + cc * 8);
            }
        }
        CP_COMMIT();
    };

    load_chunk(0, 0);

    const int tA[3] = {0, 0, 1};
    const int tB[3] = {2, 3, 2};

    for (int c = 0; c < KC; c++) {
        CP_WAIT0();
        __syncthreads();
        if (c + 1 < KC) load_chunk((c + 1) & 1, (c + 1) << 5);

        const int stage = c & 1;
#pragma unroll
        for (int p = 0; p < 3; p++) {
            const uint32_t baseA = su + (uint32_t)((stage * 4 + tA[p]) * DEC_TILE_B);
            const uint32_t baseB = su + (uint32_t)((stage * 4 + tB[p]) * DEC_TILE_B);
#pragma unroll
            for (int ks = 0; ks < 2; ks++) {
                uint32_t af[4][4], bg[2][4];
#pragma unroll
                for (int mt = 0; mt < 4; mt++) {
                    uint32_t addr = baseA + (uint32_t)((wm * 64 + mt * 16 + ((lane >> 3) & 1) * 8 + (lane & 7)) * 80
                                                       + (ks * 16 + (lane >> 4) * 8) * 2);
                    ldm_x4(af[mt], addr);
                }
#pragma unroll
                for (int np = 0; np < 2; np++) {
                    uint32_t addr = baseB + (uint32_t)((wn * 32 + np * 16 + ((lane >> 4) & 1) * 8 + (lane & 7)) * 80
                                                       + (ks * 16 + ((lane >> 3) & 1) * 8) * 2);
                    ldm_x4(bg[np], addr);
                }
#pragma unroll
                for (int mt = 0; mt < 4; mt++)
#pragma unroll
                    for (int nt = 0; nt < 4; nt++)
                        mma_f16(acc[mt][nt], af[mt], bg[nt >> 1][(nt & 1) * 2], bg[nt >> 1][(nt & 1) * 2 + 1]);
            }
        }
        __syncthreads();
    }

#pragma unroll
    for (int mt = 0; mt < 4; mt++) {
#pragma unroll
        for (int nt = 0; nt < 4; nt++) {
            const int r0 = bm + wm * 64 + mt * 16 + (lane >> 2);
            const int c0 = bn + wn * 32 + nt * 8 + (lane & 3) * 2;
            const float bv0 = bias[c0], bv1 = bias[c0 + 1];
#pragma unroll
            for (int h = 0; h < 2; h++) {
                const int r = r0 + h * 8;
                float v0 = acc[mt][nt][h * 2 + 0] + bv0;
                float v1 = acc[mt][nt][h * 2 + 1] + bv1;
                if (RELU) { v0 = fmaxf(v0, 0.0f); v1 = fmaxf(v1, 0.0f); }
                const size_t o = (size_t)r * N + c0;
                if (!OUTPLANES) {
                    *reinterpret_cast<float2*>(Cf + o) = make_float2(v0, v1);
                } else {
                    f16 h0 = __float2half_rn(v0), h1v = __float2half_rn(v1);
                    float r0f = v0 - __half2float(h0);
                    float r1f = v1 - __half2float(h1v);
                    __half2 hp; hp.x = h0; hp.y = h1v;
                    __half2 mp; mp.x = __float2half_rn(r0f); mp.y = __float2half_rn(r1f);
                    *reinterpret_cast<__half2*>(Ch + o) = hp;
                    *reinterpret_cast<__half2*>(Cm + o) = mp;
                }
            }
        }
    }
}

// ---------------------------------------------------------------------------
// DECODER: bf16 HMMA, 2-plane, 3-product fused (byte-identical to round 7)
// ---------------------------------------------------------------------------
template <bool RELU, int OUTP>
__global__ __launch_bounds__(256, 2)
void gemm_hmma_kernel(const bf16* __restrict__ A0, const bf16* __restrict__ A1,
                      const bf16* __restrict__ B0, const bf16* __restrict__ B1,
                      const float* __restrict__ bias,
                      float* __restrict__ Cf,
                      bf16* __restrict__ Ch, bf16* __restrict__ Cm,
                      int N, int K) {
    extern __shared__ char dsm[];
    const uint32_t su = smem_u32(dsm);

    const int tid = threadIdx.x;
    const int wid = tid >> 5, lane = tid & 31;
    const int wm = wid >> 2, wn = wid & 3;
    const int bn = blockIdx.x * 128, bm = blockIdx.y * 128;
    const int KC = K >> 5;

    const bf16* P[4] = { A0 + (size_t)bm * K, A1 + (size_t)bm * K,
                         B0 + (size_t)bn * K, B1 + (size_t)bn * K };

    float acc[4][4][4];
#pragma unroll
    for (int i = 0; i < 4; i++)
#pragma unroll
        for (int j = 0; j < 4; j++)
#pragma unroll
            for (int q = 0; q < 4; q++) acc[i][j][q] = 0.0f;

    auto load_chunk = [&](int stage, int k0) {
#pragma unroll
        for (int t = 0; t < 4; t++) {
            const bf16* src = P[t];
#pragma unroll
            for (int j = 0; j < 2; j++) {
                int ch = j * 256 + tid;
                int r = ch >> 2, cc = ch & 3;
                uint32_t off = (uint32_t)((stage * 4 + t) * DEC_TILE_B + r * 80 + cc * 16);
                cp16(su + off, src + (size_t)r * K + k0 + cc * 8);
            }
        }
        CP_COMMIT();
    };

    load_chunk(0, 0);

    const int tA[3] = {0, 0, 1};
    const int tB[3] = {2, 3, 2};

    for (int c = 0; c < KC; c++) {
        CP_WAIT0();
        __syncthreads();
        if (c + 1 < KC) load_chunk((c + 1) & 1, (c + 1) << 5);

        const int stage = c & 1;
#pragma unroll
        for (int p = 0; p < 3; p++) {
            const uint32_t baseA = su + (uint32_t)((stage * 4 + tA[p]) * DEC_TILE_B);
            const uint32_t baseB = su + (uint32_t)((stage * 4 + tB[p]) * DEC_TILE_B);
#pragma unroll
            for (int ks = 0; ks < 2; ks++) {
                uint32_t af[4][4], bg[2][4];
#pragma unroll
                for (int mt = 0; mt < 4; mt++) {
                    uint32_t addr = baseA + (uint32_t)((wm * 64 + mt * 16 + ((lane >> 3) & 1) * 8 + (lane & 7)) * 80
                                                       + (ks * 16 + (lane >> 4) * 8) * 2);
                    ldm_x4(af[mt], addr);
                }
#pragma unroll
                for (int np = 0; np < 2; np++) {
                    uint32_t addr = baseB + (uint32_t)((wn * 32 + np * 16 + ((lane >> 4) & 1) * 8 + (lane & 7)) * 80
                                                       + (ks * 16 + ((lane >> 3) & 1) * 8) * 2);
                    ldm_x4(bg[np], addr);
                }
#pragma unroll
                for (int mt = 0; mt < 4; mt++)
#pragma unroll
                    for (int nt = 0; nt < 4; nt++)
                        mma_bf16(acc[mt][nt], af[mt], bg[nt >> 1][(nt & 1) * 2], bg[nt >> 1][(nt & 1) * 2 + 1]);
            }
        }
        __syncthreads();
    }

#pragma unroll
    for (int mt = 0; mt < 4; mt++) {
#pragma unroll
        for (int nt = 0; nt < 4; nt++) {
            const int r0 = bm + wm * 64 + mt * 16 + (lane >> 2);
            const int c0 = bn + wn * 32 + nt * 8 + (lane & 3) * 2;
            const float bv0 = bias[c0], bv1 = bias[c0 + 1];
#pragma unroll
            for (int h = 0; h < 2; h++) {
                const int r = r0 + h * 8;
                float v0 = acc[mt][nt][h * 2 + 0] + bv0;
                float v1 = acc[mt][nt][h * 2 + 1] + bv1;
                if (RELU) { v0 = fmaxf(v0, 0.0f); v1 = fmaxf(v1, 0.0f); }
                const size_t o = (size_t)r * N + c0;
                if (OUTP == 0) {
                    *reinterpret_cast<float2*>(Cf + o) = make_float2(v0, v1);
                } else {
                    bf16 h0 = __float2bfloat16(v0), h1v = __float2bfloat16(v1);
                    float r0f = v0 - __bfloat162float(h0);
                    float r1f = v1 - __bfloat162float(h1v);
                    __nv_bfloat162 hp; hp.x = h0; hp.y = h1v;
                    __nv_bfloat162 mp; mp.x = __float2bfloat16(r0f); mp.y = __float2bfloat16(r1f);
                    *reinterpret_cast<__nv_bfloat162*>(Ch + o) = hp;
                    *reinterpret_cast<__nv_bfloat162*>(Cm + o) = mp;
                }
            }
        }
    }
}

// ---------------------------------------------------------------------------
// Splits (fp16 residual now UNSCALED)
// ---------------------------------------------------------------------------
__global__ void split2h_kernel(const float* __restrict__ src,
                               f16* __restrict__ h, f16* __restrict__ m, int n) {
    int i = blockIdx.x * blockDim.x + threadIdx.x;
    if (i < n) {
        float v = src[i];
        f16 a = __float2half_rn(v);
        float r1 = v - __half2float(a);
        h[i] = a; m[i] = __float2half_rn(r1);
    }
}
__global__ void split2_kernel(const float* __restrict__ src,
                              bf16* __restrict__ h, bf16* __restrict__ m, int n) {
    int i = blockIdx.x * blockDim.x + threadIdx.x;
    if (i < n) {
        float v = src[i];
        bf16 a = __float2bfloat16(v);
        float r1 = v - __bfloat162float(a);
        h[i] = a; m[i] = __float2bfloat16(r1);
    }
}

// ---------------------------------------------------------------------------
// Codebook squared norms
// ---------------------------------------------------------------------------
__global__ void cnorm_kernel(const float* __restrict__ cb, float* __restrict__ cn) {
    int i = blockIdx.x * blockDim.x + threadIdx.x;
    if (i >= EMB_NUM) return;
    const float4* p = reinterpret_cast<const float4*>(cb + (size_t)i * EMB_DIM);
    float s = 0.0f;
#pragma unroll
    for (int d = 0; d < EMB_DIM / 4; d++) {
        float4 v = p[d];
        s += v.x * v.x + v.y * v.y + v.z * v.z + v.w * v.w;
    }
    cn[i] = s;
}

// ---------------------------------------------------------------------------
// VQ with gap test (byte-identical to round 10)
// ---------------------------------------------------------------------------
__global__ __launch_bounds__(256)
void vq_kernel(const float* __restrict__ z,
               const float* __restrict__ cb,
               const float* __restrict__ cn,
               bf16* __restrict__ qh, bf16* __restrict__ qm,
               int* __restrict__ flags) {
    constexpr int CHUNK = 128;
    __shared__ float sc[CHUNK][EMB_DIM];
    __shared__ float scn[CHUNK];

    const int row = blockIdx.x * blockDim.x + threadIdx.x;
    const float* zp = z + (size_t)row * EMB_DIM;

    u64 m2zP[EMB_DIM / 2];
#pragma unroll
    for (int d = 0; d < EMB_DIM / 4; d++) {
        float4 v = reinterpret_cast<const float4*>(zp)[d];
        m2zP[d * 2 + 0] = pack2f(-2.0f * v.x, -2.0f * v.y);
        m2zP[d * 2 + 1] = pack2f(-2.0f * v.z, -2.0f * v.w);
    }

    float best = 3.0e38f, best2 = 3.0e38f;
    int bidx = 0;
    for (int ch = 0; ch < EMB_NUM / CHUNK; ch++) {
        __syncthreads();
        const float4* src = reinterpret_cast<const float4*>(cb + (size_t)ch * CHUNK * EMB_DIM);
        float4* dst = reinterpret_cast<float4*>(&sc[0][0]);
        for (int i = threadIdx.x; i < CHUNK * EMB_DIM / 4; i += 256) dst[i] = src[i];
        if (threadIdx.x < CHUNK) scn[threadIdx.x] = cn[ch * CHUNK + threadIdx.x];
        __syncthreads();

        for (int j = 0; j < CHUNK; j++) {
            u64 sP = 0ull;
#pragma unroll
            for (int d = 0; d < EMB_DIM / 4; d++) {
                float4 cc = reinterpret_cast<const float4*>(&sc[j][0])[d];
                sP = ffma2(pack2f(cc.x, cc.y), m2zP[d * 2 + 0], sP);
                sP = ffma2(pack2f(cc.z, cc.w), m2zP[d * 2 + 1], sP);
            }
            float lo, hi;
            unpack2f(sP, lo, hi);
            float s = scn[j] + lo + hi;
            if (s < best) { best2 = best; best = s; bidx = ch * CHUNK + j; }
            else if (s < best2) { best2 = s; }
        }
    }

    flags[row] = (best2 - best < FLAG_T) ? 1 : 0;

    const float* cp = cb + (size_t)bidx * EMB_DIM;
#pragma unroll
    for (int d = 0; d < EMB_DIM; d++) {
        float zz = zp[d];
        float v = zz + (cp[d] - zz);
        bf16 a = __float2bfloat16(v);
        float r1 = v - __bfloat162float(a);
        size_t o = (size_t)row * EMB_DIM + d;
        qh[o] = a; qm[o] = __float2bfloat16(r1);
    }
}

// ---------------------------------------------------------------------------
// REPAIR (byte-identical to round 10)
// ---------------------------------------------------------------------------
__global__ __launch_bounds__(256)
void repair_kernel(const float* __restrict__ x,
                   const float* __restrict__ w0, const float* __restrict__ b0,
                   const float* __restrict__ w1, const float* __restrict__ b1,
                   const float* __restrict__ zw, const float* __restrict__ zb,
                   const float* __restrict__ cb, const float* __restrict__ cn,
                   const int* __restrict__ flags,
                   bf16* __restrict__ qh, bf16* __restrict__ qm) {
    const int row = blockIdx.x;
    const int f0 = flags[row * 4 + 0], f1 = flags[row * 4 + 1];
    const int f2 = flags[row * 4 + 2], f3 = flags[row * 4 + 3];
    if (!(f0 | f1 | f2 | f3)) return;

    __shared__ float xs[2048];
    __shared__ float h1s[1024];
    __shared__ float h2s[512];
    __shared__ float zs[256];
    __shared__ float rbest[256];
    __shared__ int ridx[256];

    const int t = threadIdx.x;

    {
        const float4* xr = reinterpret_cast<const float4*>(x + (size_t)row * 2048);
        float4* xd = reinterpret_cast<float4*>(xs);
        for (int i = t; i < 512; i += 256) xd[i] = xr[i];
    }
    __syncthreads();

    {
        const float* r0 = w0 + (size_t)(t      ) * 2048;
        const float* r1 = w0 + (size_t)(t + 256) * 2048;
        const float* r2 = w0 + (size_t)(t + 512) * 2048;
        const float* r3 = w0 + (size_t)(t + 768) * 2048;
        float a0 = 0.0f, a1 = 0.0f, a2 = 0.0f, a3 = 0.0f;
        for (int k = 0; k < 2048; k += 4) {
            float4 xv = *reinterpret_cast<const float4*>(xs + k);
            float4 v0 = *reinterpret_cast<const float4*>(r0 + k);
            float4 v1 = *reinterpret_cast<const float4*>(r1 + k);
            float4 v2 = *reinterpret_cast<const float4*>(r2 + k);
            float4 v3 = *reinterpret_cast<const float4*>(r3 + k);
            a0 = fmaf(xv.x, v0.x, a0); a0 = fmaf(xv.y, v0.y, a0);
            a0 = fmaf(xv.z, v0.z, a0); a0 = fmaf(xv.w, v0.w, a0);
            a1 = fmaf(xv.x, v1.x, a1); a1 = fmaf(xv.y, v1.y, a1);
            a1 = fmaf(xv.z, v1.z, a1); a1 = fmaf(xv.w, v1.w, a1);
            a2 = fmaf(xv.x, v2.x, a2); a2 = fmaf(xv.y, v2.y, a2);
            a2 = fmaf(xv.z, v2.z, a2); a2 = fmaf(xv.w, v2.w, a2);
            a3 = fmaf(xv.x, v3.x, a3); a3 = fmaf(xv.y, v3.y, a3);
            a3 = fmaf(xv.z, v3.z, a3); a3 = fmaf(xv.w, v3.w, a3);
        }
        h1s[t      ] = fmaxf(a0 + b0[t      ], 0.0f);
        h1s[t + 256] = fmaxf(a1 + b0[t + 256], 0.0f);
        h1s[t + 512] = fmaxf(a2 + b0[t + 512], 0.0f);
        h1s[t + 768] = fmaxf(a3 + b0[t + 768], 0.0f);
    }
    __syncthreads();

    {
        const float* r0 = w1 + (size_t)(t      ) * 1024;
        const float* r1 = w1 + (size_t)(t + 256) * 1024;
        float a0 = 0.0f, a1 = 0.0f;
        for (int k = 0; k < 1024; k += 4) {
            float4 hv = *reinterpret_cast<const float4*>(h1s + k);
            float4 v0 = *reinterpret_cast<const float4*>(r0 + k);
            float4 v1 = *reinterpret_cast<const float4*>(r1 + k);
            a0 = fmaf(hv.x, v0.x, a0); a0 = fmaf(hv.y, v0.y, a0);
            a0 = fmaf(hv.z, v0.z, a0); a0 = fmaf(hv.w, v0.w, a0);
            a1 = fmaf(hv.x, v1.x, a1); a1 = fmaf(hv.y, v1.y, a1);
            a1 = fmaf(hv.z, v1.z, a1); a1 = fmaf(hv.w, v1.w, a1);
        }
        h2s[t      ] = fmaxf(a0 + b1[t      ], 0.0f);
        h2s[t + 256] = fmaxf(a1 + b1[t + 256], 0.0f);
    }
    __syncthreads();

    {
        const float* wr = zw + (size_t)t * 512;
        float acc = 0.0f;
        for (int k = 0; k < 512; k += 4) {
            float4 hv = *reinterpret_cast<const float4*>(h2s + k);
            float4 wv = *reinterpret_cast<const float4*>(wr + k);
            acc = fmaf(hv.x, wv.x, acc); acc = fmaf(hv.y, wv.y, acc);
            acc = fmaf(hv.z, wv.z, acc); acc = fmaf(hv.w, wv.w, acc);
        }
        zs[t] = acc + zb[t];
    }
    __syncthreads();

    const int gf[4] = {f0, f1, f2, f3};
#pragma unroll
    for (int g = 0; g < 4; g++) {
        if (!gf[g]) continue;
        const float* zg = zs + g * EMB_DIM;
        u64 m2zP[EMB_DIM / 2];
#pragma unroll
        for (int d = 0; d < EMB_DIM / 4; d++) {
            float4 v = *reinterpret_cast<const float4*>(zg + d * 4);
            m2zP[d * 2 + 0] = pack2f(-2.0f * v.x, -2.0f * v.y);
            m2zP[d * 2 + 1] = pack2f(-2.0f * v.z, -2.0f * v.w);
        }
        float best = 3.0e38f;
        int bidx = 0;
        for (int jj = 0; jj < 4; jj++) {
            int j = jj * 256 + t;
            u64 sP = 0ull;
            const float4* cc4 = reinterpret_cast<const float4*>(cb + (size_t)j * EMB_DIM);
#pragma unroll
            for (int d = 0; d < EMB_DIM / 4; d++) {
                float4 cc = cc4[d];
                sP = ffma2(pack2f(cc.x, cc.y), m2zP[d * 2 + 0], sP);
                sP = ffma2(pack2f(cc.z, cc.w), m2zP[d * 2 + 1], sP);
            }
            float lo, hi;
            unpack2f(sP, lo, hi);
            float s = cn[j] + lo + hi;
            if (s < best || (s == best && j < bidx)) { best = s; bidx = j; }
        }
        rbest[t] = best; ridx[t] = bidx;
        __syncthreads();
        for (int s2 = 128; s2 > 0; s2 >>= 1) {
            if (t < s2) {
                float ob = rbest[t + s2]; int oi = ridx[t + s2];
                if (ob < rbest[t] || (ob == rbest[t] && oi < ridx[t])) { rbest[t] = ob; ridx[t] = oi; }
            }
            __syncthreads();
        }
        const int fin = ridx[0];
        if (t < EMB_DIM) {
            float zz = zg[t];
            float v = zz + (cb[(size_t)fin * EMB_DIM + t] - zz);
            bf16 a = __float2bfloat16(v);
            float r1 = v - __bfloat162float(a);
            size_t o = ((size_t)row * 4 + g) * EMB_DIM + t;
            qh[o] = a; qm[o] = __float2bfloat16(r1);
        }
        __syncthreads();
    }
}

// ---------------------------------------------------------------------------
// Host launch
// ---------------------------------------------------------------------------
template <bool RELU, bool OUTPLANES>
static inline void launch_encH(const f16* Ah, const f16* Am,
                               const f16* Bh, const f16* Bm,
                               const float* bias, float* Cf, f16* Ch, f16* Cm,
                               int N, int K) {
    cudaFuncSetAttribute(enc_hmma_kernel<RELU, OUTPLANES>,
                         cudaFuncAttributeMaxDynamicSharedMemorySize, DEC_SMEM);
    dim3 grid(N / 128, M_ROWS / 128);
    enc_hmma_kernel<RELU, OUTPLANES><<<grid, 256, DEC_SMEM>>>(Ah, Am, Bh, Bm, bias, Cf, Ch, Cm, N, K);
}

template <bool RELU, int OUTP>
static inline void launch_dec(const bf16* A0, const bf16* A1,
                              const bf16* B0, const bf16* B1,
                              const float* bias, float* Cf, bf16* Ch, bf16* Cm,
                              int N, int K) {
    cudaFuncSetAttribute(gemm_hmma_kernel<RELU, OUTP>,
                         cudaFuncAttributeMaxDynamicSharedMemorySize, DEC_SMEM);
    dim3 grid(N / 128, M_ROWS / 128);
    gemm_hmma_kernel<RELU, OUTP><<<grid, 256, DEC_SMEM>>>(A0, A1, B0, B1, bias, Cf, Ch, Cm, N, K);
}

extern "C" void kernel_launch(void* const* d_in, const int* in_sizes, int n_in,
                              void* d_out, int out_size) {
    const float* x        = (const float*)d_in[0];
    const float* enc0_w   = (const float*)d_in[1];
    const float* enc0_b   = (const float*)d_in[2];
    const float* enc1_w   = (const float*)d_in[3];
    const float* enc1_b   = (const float*)d_in[4];
    const float* z_w      = (const float*)d_in[5];
    const float* z_b      = (const float*)d_in[6];
    const float* codebook = (const float*)d_in[7];
    const float* dec0_w   = (const float*)d_in[8];
    const float* dec0_b   = (const float*)d_in[9];
    const float* dec1_w   = (const float*)d_in[10];
    const float* dec1_b   = (const float*)d_in[11];
    const float* out_w    = (const float*)d_in[12];
    const float* out_b    = (const float*)d_in[13];
    float* out = (float*)d_out;

    f16 *xh, *xm, *w0h, *w0m, *w1h, *w1m, *h1h, *h1m;
    cudaGetSymbolAddress((void**)&xh, g_xh);
    cudaGetSymbolAddress((void**)&xm, g_xm);
    cudaGetSymbolAddress((void**)&w0h, g_w0h);
    cudaGetSymbolAddress((void**)&w0m, g_w0m);
    cudaGetSymbolAddress((void**)&w1h, g_w1h);
    cudaGetSymbolAddress((void**)&w1m, g_w1m);
    cudaGetSymbolAddress((void**)&h1h, g_h1h);
    cudaGetSymbolAddress((void**)&h1m, g_h1m);
    float *h2, *z, *cn;
    int* flags;
    cudaGetSymbolAddress((void**)&h2, g_h2);
    cudaGetSymbolAddress((void**)&z,  g_z);
    cudaGetSymbolAddress((void**)&cn, g_cn);
    cudaGetSymbolAddress((void**)&flags, g_flags);
    bf16 (*zq)[8192 * 256];   cudaGetSymbolAddress((void**)&zq, g_zq);
    bf16 (*d1)[8192 * 512];   cudaGetSymbolAddress((void**)&d1, g_d1);
    bf16 (*d2)[8192 * 1024];  cudaGetSymbolAddress((void**)&d2, g_d2);
    bf16 (*wd0)[512 * 256];   cudaGetSymbolAddress((void**)&wd0, g_wd0);
    bf16 (*wd1)[1024 * 512];  cudaGetSymbolAddress((void**)&wd1, g_wd1);
    bf16 (*wo)[2048 * 1024];  cudaGetSymbolAddress((void**)&wo, g_wo);

    // splits
    split2h_kernel<<<(8192 * 2048 + 255) / 256, 256>>>(x, xh, xm, 8192 * 2048);
    split2h_kernel<<<(1024 * 2048 + 255) / 256, 256>>>(enc0_w, w0h, w0m, 1024 * 2048);
    split2h_kernel<<<(512 * 1024 + 255) / 256, 256>>>(enc1_w, w1h, w1m, 512 * 1024);
    split2_kernel<<<(512 * 256 + 255) / 256, 256>>>(dec0_w, wd0[0], wd0[1], 512 * 256);
    split2_kernel<<<(1024 * 512 + 255) / 256, 256>>>(dec1_w, wd1[0], wd1[1], 1024 * 512);
    split2_kernel<<<(2048 * 1024 + 255) / 256, 256>>>(out_w, wo[0], wo[1], 2048 * 1024);

    // encoder: h1, h2 via fp16 HMMA; z fp32 from h2
    launch_encH<true, true >(xh, xm, w0h, w0m, enc0_b, nullptr, h1h, h1m, 1024, 2048);
    launch_encH<true, false>(h1h, h1m, w1h, w1m, enc1_b, h2, nullptr, nullptr, 512, 1024);
    {
        dim3 grid(256 / 128, M_ROWS / 128);
        gemm_bias_kernel<128, 128, 16, 8, 8, false><<<grid, 256>>>(h2, z_w, z_b, z, M_ROWS, 256, 512);
    }

    // vector quantization with gap test, then exact repair of flagged rows
    cnorm_kernel<<<4, 256>>>(codebook, cn);
    vq_kernel<<<(M_ROWS * 256 / EMB_DIM) / 256, 256>>>(z, codebook, cn, zq[0], zq[1], flags);
    repair_kernel<<<M_ROWS, 256>>>(x, enc0_w, enc0_b, enc1_w, enc1_b, z_w, z_b,
                                   codebook, cn, flags, zq[0], zq[1]);

    // decoder (unchanged)
    launch_dec<true,  2>(zq[0], zq[1], wd0[0], wd0[1], dec0_b, nullptr, d1[0], d1[1], 512, 256);
    launch_dec<true,  2>(d1[0], d1[1], wd1[0], wd1[1], dec1_b, nullptr, d2[0], d2[1], 1024, 512);
    launch_dec<false, 0>(d2[0], d2[1], wo[0], wo[1],  out_b,  out, nullptr, nullptr, 2048, 1024);
}

// round 12
// speedup vs baseline: 2.7305x; 1.0145x over previous
#include <cuda_runtime.h>
#include <cuda_bf16.h>
#include <cuda_fp16.h>
#include <cstdint>

// ===========================================================================
// VQ-VAE forward on GB300:
//   encoder  : fp16 2-plane HMMA (h1, h2, z all on tensor pipe; merged acc)
//   VQ       : fp32 distances (u64 direct loads) + gap test -> flags (T=1e-8)
//   repair   : flagged rows recomputed in EXACT fp32 from x (proven path)
//   decoder  : bf16 HMMA 2-plane 3-product fused (proven, unchanged)
// ===========================================================================

#define M_ROWS 8192
#define EMB_NUM 1024
#define EMB_DIM 64
#define FLAG_T 1e-8f

typedef unsigned long long u64;
typedef __nv_bfloat16 bf16;
typedef __half f16;

// ---------------------------------------------------------------------------
// Static device scratch (allocation-free rule)
// ---------------------------------------------------------------------------
__device__ f16  g_xh[8192 * 2048];
__device__ f16  g_xm[8192 * 2048];
__device__ f16  g_w0h[1024 * 2048];
__device__ f16  g_w0m[1024 * 2048];
__device__ f16  g_w1h[512 * 1024];
__device__ f16  g_w1m[512 * 1024];
__device__ f16  g_wzh[256 * 512];
__device__ f16  g_wzm[256 * 512];
__device__ f16  g_h1h[8192 * 1024];
__device__ f16  g_h1m[8192 * 1024];
__device__ f16  g_h2h[8192 * 512];
__device__ f16  g_h2m[8192 * 512];
__device__ float g_z [8192 * 256];
__device__ float g_cn[EMB_NUM];
__device__ int   g_flags[32768];
__device__ bf16 g_zq[2][8192 * 256];
__device__ bf16 g_d1[2][8192 * 512];
__device__ bf16 g_d2[2][8192 * 1024];
__device__ bf16 g_wd0[2][512 * 256];
__device__ bf16 g_wd1[2][1024 * 512];
__device__ bf16 g_wo[2][2048 * 1024];

// ---------------------------------------------------------------------------
// PTX helpers
// ---------------------------------------------------------------------------
__device__ __forceinline__ uint32_t smem_u32(const void* p) {
    uint32_t a;
    asm("{ .reg .u64 t; cvta.to.shared.u64 t, %1; cvt.u32.u64 %0, t; }" : "=r"(a) : "l"(p));
    return a;
}
__device__ __forceinline__ void cp16(uint32_t dst, const void* src) {
    asm volatile("cp.async.cg.shared.global [%0], [%1], 16;" :: "r"(dst), "l"(src));
}
#define CP_COMMIT() asm volatile("cp.async.commit_group;" ::: "memory")
#define CP_WAIT0()  asm volatile("cp.async.wait_group 0;" ::: "memory")

__device__ __forceinline__ void ldm_x4(uint32_t r[4], uint32_t addr) {
    asm volatile("ldmatrix.sync.aligned.m8n8.x4.shared.b16 {%0,%1,%2,%3}, [%4];"
                 : "=r"(r[0]), "=r"(r[1]), "=r"(r[2]), "=r"(r[3]) : "r"(addr));
}
__device__ __forceinline__ void mma_bf16(float* d, const uint32_t* a, uint32_t b0, uint32_t b1) {
    asm volatile(
        "mma.sync.aligned.m16n8k16.row.col.f32.bf16.bf16.f32 "
        "{%0,%1,%2,%3}, {%4,%5,%6,%7}, {%8,%9}, {%0,%1,%2,%3};"
        : "+f"(d[0]), "+f"(d[1]), "+f"(d[2]), "+f"(d[3])
        : "r"(a[0]), "r"(a[1]), "r"(a[2]), "r"(a[3]), "r"(b0), "r"(b1));
}
__device__ __forceinline__ void mma_f16(float* d, const uint32_t* a, uint32_t b0, uint32_t b1) {
    asm volatile(
        "mma.sync.aligned.m16n8k16.row.col.f32.f16.f16.f32 "
        "{%0,%1,%2,%3}, {%4,%5,%6,%7}, {%8,%9}, {%0,%1,%2,%3};"
        : "+f"(d[0]), "+f"(d[1]), "+f"(d[2]), "+f"(d[3])
        : "r"(a[0]), "r"(a[1]), "r"(a[2]), "r"(a[3]), "r"(b0), "r"(b1));
}
__device__ __forceinline__ u64 pack2f(float lo, float hi) {
    u64 r; asm("mov.b64 %0, {%1, %2};" : "=l"(r) : "f"(lo), "f"(hi)); return r;
}
__device__ __forceinline__ void unpack2f(u64 v, float& lo, float& hi) {
    asm("mov.b64 {%0, %1}, %2;" : "=f"(lo), "=f"(hi) : "l"(v));
}
__device__ __forceinline__ u64 ffma2(u64 a, u64 b, u64 c) {
    u64 d; asm("fma.rn.f32x2 %0, %1, %2, %3;" : "=l"(d) : "l"(a), "l"(b), "l"(c)); return d;
}

// ---------------------------------------------------------------------------
// Shared tile geometry for HMMA kernels
// ---------------------------------------------------------------------------
#define DEC_TILE_B  10240
#define DEC_STAGE_B (4 * DEC_TILE_B)
#define DEC_SMEM    (2 * DEC_STAGE_B)

// ---------------------------------------------------------------------------
// ENCODER (h1/h2/z): fp16 2-plane, unscaled residuals, merged accumulator.
// 3 products (hh, hm, mh). OUTPLANES: fp16 planes out, else fp32 out.
// ---------------------------------------------------------------------------
template <bool RELU, bool OUTPLANES>
__global__ __launch_bounds__(256, 2)
void enc_hmma_kernel(const f16* __restrict__ Ah, const f16* __restrict__ Am,
                     const f16* __restrict__ Bh, const f16* __restrict__ Bm,
                     const float* __restrict__ bias,
                     float* __restrict__ Cf,
                     f16* __restrict__ Ch, f16* __restrict__ Cm,
                     int N, int K) {
    extern __shared__ char dsm[];
    const uint32_t su = smem_u32(dsm);

    const int tid = threadIdx.x;
    const int wid = tid >> 5, lane = tid & 31;
    const int wm = wid >> 2, wn = wid & 3;
    const int bn = blockIdx.x * 128, bm = blockIdx.y * 128;
    const int KC = K >> 5;

    const f16* P[4] = { Ah + (size_t)bm * K, Am + (size_t)bm * K,
                        Bh + (size_t)bn * K, Bm + (size_t)bn * K };

    float acc[4][4][4];
#pragma unroll
    for (int i = 0; i < 4; i++)
#pragma unroll
        for (int j = 0; j < 4; j++)
#pragma unroll
            for (int q = 0; q < 4; q++) acc[i][j][q] = 0.0f;

    auto load_chunk = [&](int stage, int k0) {
#pragma unroll
        for (int t = 0; t < 4; t++) {
            const f16* src = P[t];
#pragma unroll
            for (int j = 0; j < 2; j++) {
                int ch = j * 256 + tid;
                int r = ch >> 2, cc = ch & 3;
                uint32_t off = (uint32_t)((stage * 4 + t) * DEC_TILE_B + r * 80 + cc * 16);
                cp16(su + off, src + (size_t)r * K + k0 + cc * 8);
            }
        }
        CP_COMMIT();
    };

    load_chunk(0, 0);

    const int tA[3] = {0, 0, 1};
    const int tB[3] = {2, 3, 2};

    for (int c = 0; c < KC; c++) {
        CP_WAIT0();
        __syncthreads();
        if (c + 1 < KC) load_chunk((c + 1) & 1, (c + 1) << 5);

        const int stage = c & 1;
#pragma unroll
        for (int p = 0; p < 3; p++) {
            const uint32_t baseA = su + (uint32_t)((stage * 4 + tA[p]) * DEC_TILE_B);
            const uint32_t baseB = su + (uint32_t)((stage * 4 + tB[p]) * DEC_TILE_B);
#pragma unroll
            for (int ks = 0; ks < 2; ks++) {
                uint32_t af[4][4], bg[2][4];
#pragma unroll
                for (int mt = 0; mt < 4; mt++) {
                    uint32_t addr = baseA + (uint32_t)((wm * 64 + mt * 16 + ((lane >> 3) & 1) * 8 + (lane & 7)) * 80
                                                       + (ks * 16 + (lane >> 4) * 8) * 2);
                    ldm_x4(af[mt], addr);
                }
#pragma unroll
                for (int np = 0; np < 2; np++) {
                    uint32_t addr = baseB + (uint32_t)((wn * 32 + np * 16 + ((lane >> 4) & 1) * 8 + (lane & 7)) * 80
                                                       + (ks * 16 + ((lane >> 3) & 1) * 8) * 2);
                    ldm_x4(bg[np], addr);
                }
#pragma unroll
                for (int mt = 0; mt < 4; mt++)
#pragma unroll
                    for (int nt = 0; nt < 4; nt++)
                        mma_f16(acc[mt][nt], af[mt], bg[nt >> 1][(nt & 1) * 2], bg[nt >> 1][(nt & 1) * 2 + 1]);
            }
        }
        __syncthreads();
    }

#pragma unroll
    for (int mt = 0; mt < 4; mt++) {
#pragma unroll
        for (int nt = 0; nt < 4; nt++) {
            const int r0 = bm + wm * 64 + mt * 16 + (lane >> 2);
            const int c0 = bn + wn * 32 + nt * 8 + (lane & 3) * 2;
            const float bv0 = bias[c0], bv1 = bias[c0 + 1];
#pragma unroll
            for (int h = 0; h < 2; h++) {
                const int r = r0 + h * 8;
                float v0 = acc[mt][nt][h * 2 + 0] + bv0;
                float v1 = acc[mt][nt][h * 2 + 1] + bv1;
                if (RELU) { v0 = fmaxf(v0, 0.0f); v1 = fmaxf(v1, 0.0f); }
                const size_t o = (size_t)r * N + c0;
                if (!OUTPLANES) {
                    *reinterpret_cast<float2*>(Cf + o) = make_float2(v0, v1);
                } else {
                    f16 h0 = __float2half_rn(v0), h1v = __float2half_rn(v1);
                    float r0f = v0 - __half2float(h0);
                    float r1f = v1 - __half2float(h1v);
                    __half2 hp; hp.x = h0; hp.y = h1v;
                    __half2 mp; mp.x = __float2half_rn(r0f); mp.y = __float2half_rn(r1f);
                    *reinterpret_cast<__half2*>(Ch + o) = hp;
                    *reinterpret_cast<__half2*>(Cm + o) = mp;
                }
            }
        }
    }
}

// ---------------------------------------------------------------------------
// DECODER: bf16 HMMA, 2-plane, 3-product fused (byte-identical to round 7)
// ---------------------------------------------------------------------------
template <bool RELU, int OUTP>
__global__ __launch_bounds__(256, 2)
void gemm_hmma_kernel(const bf16* __restrict__ A0, const bf16* __restrict__ A1,
                      const bf16* __restrict__ B0, const bf16* __restrict__ B1,
                      const float* __restrict__ bias,
                      float* __restrict__ Cf,
                      bf16* __restrict__ Ch, bf16* __restrict__ Cm,
                      int N, int K) {
    extern __shared__ char dsm[];
    const uint32_t su = smem_u32(dsm);

    const int tid = threadIdx.x;
    const int wid = tid >> 5, lane = tid & 31;
    const int wm = wid >> 2, wn = wid & 3;
    const int bn = blockIdx.x * 128, bm = blockIdx.y * 128;
    const int KC = K >> 5;

    const bf16* P[4] = { A0 + (size_t)bm * K, A1 + (size_t)bm * K,
                         B0 + (size_t)bn * K, B1 + (size_t)bn * K };

    float acc[4][4][4];
#pragma unroll
    for (int i = 0; i < 4; i++)
#pragma unroll
        for (int j = 0; j < 4; j++)
#pragma unroll
            for (int q = 0; q < 4; q++) acc[i][j][q] = 0.0f;

    auto load_chunk = [&](int stage, int k0) {
#pragma unroll
        for (int t = 0; t < 4; t++) {
            const bf16* src = P[t];
#pragma unroll
            for (int j = 0; j < 2; j++) {
                int ch = j * 256 + tid;
                int r = ch >> 2, cc = ch & 3;
                uint32_t off = (uint32_t)((stage * 4 + t) * DEC_TILE_B + r * 80 + cc * 16);
                cp16(su + off, src + (size_t)r * K + k0 + cc * 8);
            }
        }
        CP_COMMIT();
    };

    load_chunk(0, 0);

    const int tA[3] = {0, 0, 1};
    const int tB[3] = {2, 3, 2};

    for (int c = 0; c < KC; c++) {
        CP_WAIT0();
        __syncthreads();
        if (c + 1 < KC) load_chunk((c + 1) & 1, (c + 1) << 5);

        const int stage = c & 1;
#pragma unroll
        for (int p = 0; p < 3; p++) {
            const uint32_t baseA = su + (uint32_t)((stage * 4 + tA[p]) * DEC_TILE_B);
            const uint32_t baseB = su + (uint32_t)((stage * 4 + tB[p]) * DEC_TILE_B);
#pragma unroll
            for (int ks = 0; ks < 2; ks++) {
                uint32_t af[4][4], bg[2][4];
#pragma unroll
                for (int mt = 0; mt < 4; mt++) {
                    uint32_t addr = baseA + (uint32_t)((wm * 64 + mt * 16 + ((lane >> 3) & 1) * 8 + (lane & 7)) * 80
                                                       + (ks * 16 + (lane >> 4) * 8) * 2);
                    ldm_x4(af[mt], addr);
                }
#pragma unroll
                for (int np = 0; np < 2; np++) {
                    uint32_t addr = baseB + (uint32_t)((wn * 32 + np * 16 + ((lane >> 4) & 1) * 8 + (lane & 7)) * 80
                                                       + (ks * 16 + ((lane >> 3) & 1) * 8) * 2);
                    ldm_x4(bg[np], addr);
                }
#pragma unroll
                for (int mt = 0; mt < 4; mt++)
#pragma unroll
                    for (int nt = 0; nt < 4; nt++)
                        mma_bf16(acc[mt][nt], af[mt], bg[nt >> 1][(nt & 1) * 2], bg[nt >> 1][(nt & 1) * 2 + 1]);
            }
        }
        __syncthreads();
    }

#pragma unroll
    for (int mt = 0; mt < 4; mt++) {
#pragma unroll
        for (int nt = 0; nt < 4; nt++) {
            const int r0 = bm + wm * 64 + mt * 16 + (lane >> 2);
            const int c0 = bn + wn * 32 + nt * 8 + (lane & 3) * 2;
            const float bv0 = bias[c0], bv1 = bias[c0 + 1];
#pragma unroll
            for (int h = 0; h < 2; h++) {
                const int r = r0 + h * 8;
                float v0 = acc[mt][nt][h * 2 + 0] + bv0;
                float v1 = acc[mt][nt][h * 2 + 1] + bv1;
                if (RELU) { v0 = fmaxf(v0, 0.0f); v1 = fmaxf(v1, 0.0f); }
                const size_t o = (size_t)r * N + c0;
                if (OUTP == 0) {
                    *reinterpret_cast<float2*>(Cf + o) = make_float2(v0, v1);
                } else {
                    bf16 h0 = __float2bfloat16(v0), h1v = __float2bfloat16(v1);
                    float r0f = v0 - __bfloat162float(h0);
                    float r1f = v1 - __bfloat162float(h1v);
                    __nv_bfloat162 hp; hp.x = h0; hp.y = h1v;
                    __nv_bfloat162 mp; mp.x = __float2bfloat16(r0f); mp.y = __float2bfloat16(r1f);
                    *reinterpret_cast<__nv_bfloat162*>(Ch + o) = hp;
                    *reinterpret_cast<__nv_bfloat162*>(Cm + o) = mp;
                }
            }
        }
    }
}

// ---------------------------------------------------------------------------
// Splits
// ---------------------------------------------------------------------------
__global__ void split2h_kernel(const float* __restrict__ src,
                               f16* __restrict__ h, f16* __restrict__ m, int n) {
    int i = blockIdx.x * blockDim.x + threadIdx.x;
    if (i < n) {
        float v = src[i];
        f16 a = __float2half_rn(v);
        float r1 = v - __half2float(a);
        h[i] = a; m[i] = __float2half_rn(r1);
    }
}
__global__ void split2_kernel(const float* __restrict__ src,
                              bf16* __restrict__ h, bf16* __restrict__ m, int n) {
    int i = blockIdx.x * blockDim.x + threadIdx.x;
    if (i < n) {
        float v = src[i];
        bf16 a = __float2bfloat16(v);
        float r1 = v - __bfloat162float(a);
        h[i] = a; m[i] = __float2bfloat16(r1);
    }
}

// ---------------------------------------------------------------------------
// Codebook squared norms
// ---------------------------------------------------------------------------
__global__ void cnorm_kernel(const float* __restrict__ cb, float* __restrict__ cn) {
    int i = blockIdx.x * blockDim.x + threadIdx.x;
    if (i >= EMB_NUM) return;
    const float4* p = reinterpret_cast<const float4*>(cb + (size_t)i * EMB_DIM);
    float s = 0.0f;
#pragma unroll
    for (int d = 0; d < EMB_DIM / 4; d++) {
        float4 v = p[d];
        s += v.x * v.x + v.y * v.y + v.z * v.z + v.w * v.w;
    }
    cn[i] = s;
}

// ---------------------------------------------------------------------------
// VQ with gap test. Inner loop loads code pairs as u64 directly (bitwise
// identical to the previous pack2f of the two floats) — halves issue count.
// ---------------------------------------------------------------------------
__global__ __launch_bounds__(256)
void vq_kernel(const float* __restrict__ z,
               const float* __restrict__ cb,
               const float* __restrict__ cn,
               bf16* __restrict__ qh, bf16* __restrict__ qm,
               int* __restrict__ flags) {
    constexpr int CHUNK = 128;
    __shared__ float sc[CHUNK][EMB_DIM];
    __shared__ float scn[CHUNK];

    const int row = blockIdx.x * blockDim.x + threadIdx.x;
    const float* zp = z + (size_t)row * EMB_DIM;

    u64 m2zP[EMB_DIM / 2];
#pragma unroll
    for (int d = 0; d < EMB_DIM / 4; d++) {
        float4 v = reinterpret_cast<const float4*>(zp)[d];
        m2zP[d * 2 + 0] = pack2f(-2.0f * v.x, -2.0f * v.y);
        m2zP[d * 2 + 1] = pack2f(-2.0f * v.z, -2.0f * v.w);
    }

    float best = 3.0e38f, best2 = 3.0e38f;
    int bidx = 0;
    for (int ch = 0; ch < EMB_NUM / CHUNK; ch++) {
        __syncthreads();
        const float4* src = reinterpret_cast<const float4*>(cb + (size_t)ch * CHUNK * EMB_DIM);
        float4* dst = reinterpret_cast<float4*>(&sc[0][0]);
        for (int i = threadIdx.x; i < CHUNK * EMB_DIM / 4; i += 256) dst[i] = src[i];
        if (threadIdx.x < CHUNK) scn[threadIdx.x] = cn[ch * CHUNK + threadIdx.x];
        __syncthreads();

        for (int j = 0; j < CHUNK; j++) {
            const u64* cc8 = reinterpret_cast<const u64*>(&sc[j][0]);
            u64 sP = 0ull;
#pragma unroll
            for (int d = 0; d < EMB_DIM / 2; d++)
                sP = ffma2(cc8[d], m2zP[d], sP);
            float lo, hi;
            unpack2f(sP, lo, hi);
            float s = scn[j] + lo + hi;
            if (s < best) { best2 = best; best = s; bidx = ch * CHUNK + j; }
            else if (s < best2) { best2 = s; }
        }
    }

    flags[row] = (best2 - best < FLAG_T) ? 1 : 0;

    const float* cp = cb + (size_t)bidx * EMB_DIM;
#pragma unroll
    for (int d = 0; d < EMB_DIM; d++) {
        float zz = zp[d];
        float v = zz + (cp[d] - zz);
        bf16 a = __float2bfloat16(v);
        float r1 = v - __bfloat162float(a);
        size_t o = (size_t)row * EMB_DIM + d;
        qh[o] = a; qm[o] = __float2bfloat16(r1);
    }
}

// ---------------------------------------------------------------------------
// REPAIR: exact fp32 recompute of flagged rows (proven round-10 path; the
// distance loop now uses direct u64 loads — bitwise identical values).
// ---------------------------------------------------------------------------
__global__ __launch_bounds__(256)
void repair_kernel(const float* __restrict__ x,
                   const float* __restrict__ w0, const float* __restrict__ b0,
                   const float* __restrict__ w1, const float* __restrict__ b1,
                   const float* __restrict__ zw, const float* __restrict__ zb,
                   const float* __restrict__ cb, const float* __restrict__ cn,
                   const int* __restrict__ flags,
                   bf16* __restrict__ qh, bf16* __restrict__ qm) {
    const int row = blockIdx.x;
    const int f0 = flags[row * 4 + 0], f1 = flags[row * 4 + 1];
    const int f2 = flags[row * 4 + 2], f3 = flags[row * 4 + 3];
    if (!(f0 | f1 | f2 | f3)) return;

    __shared__ float xs[2048];
    __shared__ float h1s[1024];
    __shared__ float h2s[512];
    __shared__ float zs[256];
    __shared__ float rbest[256];
    __shared__ int ridx[256];

    const int t = threadIdx.x;

    {
        const float4* xr = reinterpret_cast<const float4*>(x + (size_t)row * 2048);
        float4* xd = reinterpret_cast<float4*>(xs);
        for (int i = t; i < 512; i += 256) xd[i] = xr[i];
    }
    __syncthreads();

    {
        const float* r0 = w0 + (size_t)(t      ) * 2048;
        const float* r1 = w0 + (size_t)(t + 256) * 2048;
        const float* r2 = w0 + (size_t)(t + 512) * 2048;
        const float* r3 = w0 + (size_t)(t + 768) * 2048;
        float a0 = 0.0f, a1 = 0.0f, a2 = 0.0f, a3 = 0.0f;
        for (int k = 0; k < 2048; k += 4) {
            float4 xv = *reinterpret_cast<const float4*>(xs + k);
            float4 v0 = *reinterpret_cast<const float4*>(r0 + k);
            float4 v1 = *reinterpret_cast<const float4*>(r1 + k);
            float4 v2 = *reinterpret_cast<const float4*>(r2 + k);
            float4 v3 = *reinterpret_cast<const float4*>(r3 + k);
            a0 = fmaf(xv.x, v0.x, a0); a0 = fmaf(xv.y, v0.y, a0);
            a0 = fmaf(xv.z, v0.z, a0); a0 = fmaf(xv.w, v0.w, a0);
            a1 = fmaf(xv.x, v1.x, a1); a1 = fmaf(xv.y, v1.y, a1);
            a1 = fmaf(xv.z, v1.z, a1); a1 = fmaf(xv.w, v1.w, a1);
            a2 = fmaf(xv.x, v2.x, a2); a2 = fmaf(xv.y, v2.y, a2);
            a2 = fmaf(xv.z, v2.z, a2); a2 = fmaf(xv.w, v2.w, a2);
            a3 = fmaf(xv.x, v3.x, a3); a3 = fmaf(xv.y, v3.y, a3);
            a3 = fmaf(xv.z, v3.z, a3); a3 = fmaf(xv.w, v3.w, a3);
        }
        h1s[t      ] = fmaxf(a0 + b0[t      ], 0.0f);
        h1s[t + 256] = fmaxf(a1 + b0[t + 256], 0.0f);
        h1s[t + 512] = fmaxf(a2 + b0[t + 512], 0.0f);
        h1s[t + 768] = fmaxf(a3 + b0[t + 768], 0.0f);
    }
    __syncthreads();

    {
        const float* r0 = w1 + (size_t)(t      ) * 1024;
        const float* r1 = w1 + (size_t)(t + 256) * 1024;
        float a0 = 0.0f, a1 = 0.0f;
        for (int k = 0; k < 1024; k += 4) {
            float4 hv = *reinterpret_cast<const float4*>(h1s + k);
            float4 v0 = *reinterpret_cast<const float4*>(r0 + k);
            float4 v1 = *reinterpret_cast<const float4*>(r1 + k);
            a0 = fmaf(hv.x, v0.x, a0); a0 = fmaf(hv.y, v0.y, a0);
            a0 = fmaf(hv.z, v0.z, a0); a0 = fmaf(hv.w, v0.w, a0);
            a1 = fmaf(hv.x, v1.x, a1); a1 = fmaf(hv.y, v1.y, a1);
            a1 = fmaf(hv.z, v1.z, a1); a1 = fmaf(hv.w, v1.w, a1);
        }
        h2s[t      ] = fmaxf(a0 + b1[t      ], 0.0f);
        h2s[t + 256] = fmaxf(a1 + b1[t + 256], 0.0f);
    }
    __syncthreads();

    {
        const float* wr = zw + (size_t)t * 512;
        float acc = 0.0f;
        for (int k = 0; k < 512; k += 4) {
            float4 hv = *reinterpret_cast<const float4*>(h2s + k);
            float4 wv = *reinterpret_cast<const float4*>(wr + k);
            acc = fmaf(hv.x, wv.x, acc); acc = fmaf(hv.y, wv.y, acc);
            acc = fmaf(hv.z, wv.z, acc); acc = fmaf(hv.w, wv.w, acc);
        }
        zs[t] = acc + zb[t];
    }
    __syncthreads();

    const int gf[4] = {f0, f1, f2, f3};
#pragma unroll
    for (int g = 0; g < 4; g++) {
        if (!gf[g]) continue;
        const float* zg = zs + g * EMB_DIM;
        u64 m2zP[EMB_DIM / 2];
#pragma unroll
        for (int d = 0; d < EMB_DIM / 4; d++) {
            float4 v = *reinterpret_cast<const float4*>(zg + d * 4);
            m2zP[d * 2 + 0] = pack2f(-2.0f * v.x, -2.0f * v.y);
            m2zP[d * 2 + 1] = pack2f(-2.0f * v.z, -2.0f * v.w);
        }
        float best = 3.0e38f;
        int bidx = 0;
        for (int jj = 0; jj < 4; jj++) {
            int j = jj * 256 + t;
            u64 sP = 0ull;
            const u64* cc8 = reinterpret_cast<const u64*>(cb + (size_t)j * EMB_DIM);
#pragma unroll
            for (int d = 0; d < EMB_DIM / 2; d++)
                sP = ffma2(cc8[d], m2zP[d], sP);
            float lo, hi;
            unpack2f(sP, lo, hi);
            float s = cn[j] + lo + hi;
            if (s < best || (s == best && j < bidx)) { best = s; bidx = j; }
        }
        rbest[t] = best; ridx[t] = bidx;
        __syncthreads();
        for (int s2 = 128; s2 > 0; s2 >>= 1) {
            if (t < s2) {
                float ob = rbest[t + s2]; int oi = ridx[t + s2];
                if (ob < rbest[t] || (ob == rbest[t] && oi < ridx[t])) { rbest[t] = ob; ridx[t] = oi; }
            }
            __syncthreads();
        }
        const int fin = ridx[0];
        if (t < EMB_DIM) {
            float zz = zg[t];
            float v = zz + (cb[(size_t)fin * EMB_DIM + t] - zz);
            bf16 a = __float2bfloat16(v);
            float r1 = v - __bfloat162float(a);
            size_t o = ((size_t)row * 4 + g) * EMB_DIM + t;
            qh[o] = a; qm[o] = __float2bfloat16(r1);
        }
        __syncthreads();
    }
}

// ---------------------------------------------------------------------------
// Host launch
// ---------------------------------------------------------------------------
template <bool RELU, bool OUTPLANES>
static inline void launch_encH(const f16* Ah, const f16* Am,
                               const f16* Bh, const f16* Bm,
                               const float* bias, float* Cf, f16* Ch, f16* Cm,
                               int N, int K) {
    cudaFuncSetAttribute(enc_hmma_kernel<RELU, OUTPLANES>,
                         cudaFuncAttributeMaxDynamicSharedMemorySize, DEC_SMEM);
    dim3 grid(N / 128, M_ROWS / 128);
    enc_hmma_kernel<RELU, OUTPLANES><<<grid, 256, DEC_SMEM>>>(Ah, Am, Bh, Bm, bias, Cf, Ch, Cm, N, K);
}

template <bool RELU, int OUTP>
static inline void launch_dec(const bf16* A0, const bf16* A1,
                              const bf16* B0, const bf16* B1,
                              const float* bias, float* Cf, bf16* Ch, bf16* Cm,
                              int N, int K) {
    cudaFuncSetAttribute(gemm_hmma_kernel<RELU, OUTP>,
                         cudaFuncAttributeMaxDynamicSharedMemorySize, DEC_SMEM);
    dim3 grid(N / 128, M_ROWS / 128);
    gemm_hmma_kernel<RELU, OUTP><<<grid, 256, DEC_SMEM>>>(A0, A1, B0, B1, bias, Cf, Ch, Cm, N, K);
}

extern "C" void kernel_launch(void* const* d_in, const int* in_sizes, int n_in,
                              void* d_out, int out_size) {
    const float* x        = (const float*)d_in[0];
    const float* enc0_w   = (const float*)d_in[1];
    const float* enc0_b   = (const float*)d_in[2];
    const float* enc1_w   = (const float*)d_in[3];
    const float* enc1_b   = (const float*)d_in[4];
    const float* z_w      = (const float*)d_in[5];
    const float* z_b      = (const float*)d_in[6];
    const float* codebook = (const float*)d_in[7];
    const float* dec0_w   = (const float*)d_in[8];
    const float* dec0_b   = (const float*)d_in[9];
    const float* dec1_w   = (const float*)d_in[10];
    const float* dec1_b   = (const float*)d_in[11];
    const float* out_w    = (const float*)d_in[12];
    const float* out_b    = (const float*)d_in[13];
    float* out = (float*)d_out;

    f16 *xh, *xm, *w0h, *w0m, *w1h, *w1m, *wzh, *wzm, *h1h, *h1m, *h2h, *h2m;
    cudaGetSymbolAddress((void**)&xh, g_xh);
    cudaGetSymbolAddress((void**)&xm, g_xm);
    cudaGetSymbolAddress((void**)&w0h, g_w0h);
    cudaGetSymbolAddress((void**)&w0m, g_w0m);
    cudaGetSymbolAddress((void**)&w1h, g_w1h);
    cudaGetSymbolAddress((void**)&w1m, g_w1m);
    cudaGetSymbolAddress((void**)&wzh, g_wzh);
    cudaGetSymbolAddress((void**)&wzm, g_wzm);
    cudaGetSymbolAddress((void**)&h1h, g_h1h);
    cudaGetSymbolAddress((void**)&h1m, g_h1m);
    cudaGetSymbolAddress((void**)&h2h, g_h2h);
    cudaGetSymbolAddress((void**)&h2m, g_h2m);
    float *z, *cn;
    int* flags;
    cudaGetSymbolAddress((void**)&z,  g_z);
    cudaGetSymbolAddress((void**)&cn, g_cn);
    cudaGetSymbolAddress((void**)&flags, g_flags);
    bf16 (*zq)[8192 * 256];   cudaGetSymbolAddress((void**)&zq, g_zq);
    bf16 (*d1)[8192 * 512];   cudaGetSymbolAddress((void**)&d1, g_d1);
    bf16 (*d2)[8192 * 1024];  cudaGetSymbolAddress((void**)&d2, g_d2);
    bf16 (*wd0)[512 * 256];   cudaGetSymbolAddress((void**)&wd0, g_wd0);
    bf16 (*wd1)[1024 * 512];  cudaGetSymbolAddress((void**)&wd1, g_wd1);
    bf16 (*wo)[2048 * 1024];  cudaGetSymbolAddress((void**)&wo, g_wo);

    // splits
    split2h_kernel<<<(8192 * 2048 + 255) / 256, 256>>>(x, xh, xm, 8192 * 2048);
    split2h_kernel<<<(1024 * 2048 + 255) / 256, 256>>>(enc0_w, w0h, w0m, 1024 * 2048);
    split2h_kernel<<<(512 * 1024 + 255) / 256, 256>>>(enc1_w, w1h, w1m, 512 * 1024);
    split2h_kernel<<<(256 * 512 + 255) / 256, 256>>>(z_w, wzh, wzm, 256 * 512);
    split2_kernel<<<(512 * 256 + 255) / 256, 256>>>(dec0_w, wd0[0], wd0[1], 512 * 256);
    split2_kernel<<<(1024 * 512 + 255) / 256, 256>>>(dec1_w, wd1[0], wd1[1], 1024 * 512);
    split2_kernel<<<(2048 * 1024 + 255) / 256, 256>>>(out_w, wo[0], wo[1], 2048 * 1024);

    // encoder: h1, h2, z all via fp16 HMMA
    launch_encH<true, true >(xh, xm, w0h, w0m, enc0_b, nullptr, h1h, h1m, 1024, 2048);
    launch_encH<true, true >(h1h, h1m, w1h, w1m, enc1_b, nullptr, h2h, h2m, 512, 1024);
    launch_encH<false, false>(h2h, h2m, wzh, wzm, z_b, z, nullptr, nullptr, 256, 512);

    // vector quantization with gap test, then exact repair of flagged rows
    cnorm_kernel<<<4, 256>>>(codebook, cn);
    vq_kernel<<<(M_ROWS * 256 / EMB_DIM) / 256, 256>>>(z, codebook, cn, zq[0], zq[1], flags);
    repair_kernel<<<M_ROWS, 256>>>(x, enc0_w, enc0_b, enc1_w, enc1_b, z_w, z_b,
                                   codebook, cn, flags, zq[0], zq[1]);

    // decoder (unchanged)
    launch_dec<true,  2>(zq[0], zq[1], wd0[0], wd0[1], dec0_b, nullptr, d1[0], d1[1], 512, 256);
    launch_dec<true,  2>(d1[0], d1[1], wd1[0], wd1[1], dec1_b, nullptr, d2[0], d2[1], 1024, 512);
    launch_dec<false, 0>(d2[0], d2[1], wo[0], wo[1],  out_b,  out, nullptr, nullptr, 2048, 1024);
}

// round 13
// speedup vs baseline: 2.9147x; 1.0674x over previous
#include <cuda_runtime.h>
#include <cuda_bf16.h>
#include <cuda_fp16.h>
#include <cstdint>

// ===========================================================================
// VQ-VAE forward on GB300:
//   encoder  : fp16 2-plane HMMA (h1, h2, z on tensor pipe; merged acc)
//   VQ       : fp32 distances + gap test -> flags (T=1e-8)
//   repair   : BATCHED exact-fp32 recompute of flagged rows (3 phases with
//              8-row weight reuse; bitwise-identical per-output math);
//              per-row fallback if > CAP rows flagged
//   decoder  : bf16 HMMA 2-plane 3-product fused (proven, unchanged)
// ===========================================================================

#define M_ROWS 8192
#define EMB_NUM 1024
#define EMB_DIM 64
#define FLAG_T 1e-8f
#define REP_CAP 2048

typedef unsigned long long u64;
typedef __nv_bfloat16 bf16;
typedef __half f16;

// ---------------------------------------------------------------------------
// Static device scratch (allocation-free rule)
// ---------------------------------------------------------------------------
__device__ f16  g_xh[8192 * 2048];
__device__ f16  g_xm[8192 * 2048];
__device__ f16  g_w0h[1024 * 2048];
__device__ f16  g_w0m[1024 * 2048];
__device__ f16  g_w1h[512 * 1024];
__device__ f16  g_w1m[512 * 1024];
__device__ f16  g_wzh[256 * 512];
__device__ f16  g_wzm[256 * 512];
__device__ f16  g_h1h[8192 * 1024];
__device__ f16  g_h1m[8192 * 1024];
__device__ f16  g_h2h[8192 * 512];
__device__ f16  g_h2m[8192 * 512];
__device__ float g_z [8192 * 256];
__device__ float g_cn[EMB_NUM];
__device__ int   g_flags[32768];
__device__ int   g_rlist[M_ROWS];
__device__ int   g_nrep;
__device__ float g_rh1[REP_CAP * 1024];
__device__ float g_rh2[REP_CAP * 512];
__device__ bf16 g_zq[2][8192 * 256];
__device__ bf16 g_d1[2][8192 * 512];
__device__ bf16 g_d2[2][8192 * 1024];
__device__ bf16 g_wd0[2][512 * 256];
__device__ bf16 g_wd1[2][1024 * 512];
__device__ bf16 g_wo[2][2048 * 1024];

// ---------------------------------------------------------------------------
// PTX helpers
// ---------------------------------------------------------------------------
__device__ __forceinline__ uint32_t smem_u32(const void* p) {
    uint32_t a;
    asm("{ .reg .u64 t; cvta.to.shared.u64 t, %1; cvt.u32.u64 %0, t; }" : "=r"(a) : "l"(p));
    return a;
}
__device__ __forceinline__ void cp16(uint32_t dst, const void* src) {
    asm volatile("cp.async.cg.shared.global [%0], [%1], 16;" :: "r"(dst), "l"(src));
}
#define CP_COMMIT() asm volatile("cp.async.commit_group;" ::: "memory")
#define CP_WAIT0()  asm volatile("cp.async.wait_group 0;" ::: "memory")

__device__ __forceinline__ void ldm_x4(uint32_t r[4], uint32_t addr) {
    asm volatile("ldmatrix.sync.aligned.m8n8.x4.shared.b16 {%0,%1,%2,%3}, [%4];"
                 : "=r"(r[0]), "=r"(r[1]), "=r"(r[2]), "=r"(r[3]) : "r"(addr));
}
__device__ __forceinline__ void mma_bf16(float* d, const uint32_t* a, uint32_t b0, uint32_t b1) {
    asm volatile(
        "mma.sync.aligned.m16n8k16.row.col.f32.bf16.bf16.f32 "
        "{%0,%1,%2,%3}, {%4,%5,%6,%7}, {%8,%9}, {%0,%1,%2,%3};"
        : "+f"(d[0]), "+f"(d[1]), "+f"(d[2]), "+f"(d[3])
        : "r"(a[0]), "r"(a[1]), "r"(a[2]), "r"(a[3]), "r"(b0), "r"(b1));
}
__device__ __forceinline__ void mma_f16(float* d, const uint32_t* a, uint32_t b0, uint32_t b1) {
    asm volatile(
        "mma.sync.aligned.m16n8k16.row.col.f32.f16.f16.f32 "
        "{%0,%1,%2,%3}, {%4,%5,%6,%7}, {%8,%9}, {%0,%1,%2,%3};"
        : "+f"(d[0]), "+f"(d[1]), "+f"(d[2]), "+f"(d[3])
        : "r"(a[0]), "r"(a[1]), "r"(a[2]), "r"(a[3]), "r"(b0), "r"(b1));
}
__device__ __forceinline__ u64 pack2f(float lo, float hi) {
    u64 r; asm("mov.b64 %0, {%1, %2};" : "=l"(r) : "f"(lo), "f"(hi)); return r;
}
__device__ __forceinline__ void unpack2f(u64 v, float& lo, float& hi) {
    asm("mov.b64 {%0, %1}, %2;" : "=f"(lo), "=f"(hi) : "l"(v));
}
__device__ __forceinline__ u64 ffma2(u64 a, u64 b, u64 c) {
    u64 d; asm("fma.rn.f32x2 %0, %1, %2, %3;" : "=l"(d) : "l"(a), "l"(b), "l"(c)); return d;
}

// ---------------------------------------------------------------------------
// Shared tile geometry for HMMA kernels
// ---------------------------------------------------------------------------
#define DEC_TILE_B  10240
#define DEC_STAGE_B (4 * DEC_TILE_B)
#define DEC_SMEM    (2 * DEC_STAGE_B)

// ---------------------------------------------------------------------------
// ENCODER (h1/h2/z): fp16 2-plane, unscaled residuals, merged accumulator.
// (byte-identical to passing round 12)
// ---------------------------------------------------------------------------
template <bool RELU, bool OUTPLANES>
__global__ __launch_bounds__(256, 2)
void enc_hmma_kernel(const f16* __restrict__ Ah, const f16* __restrict__ Am,
                     const f16* __restrict__ Bh, const f16* __restrict__ Bm,
                     const float* __restrict__ bias,
                     float* __restrict__ Cf,
                     f16* __restrict__ Ch, f16* __restrict__ Cm,
                     int N, int K) {
    extern __shared__ char dsm[];
    const uint32_t su = smem_u32(dsm);

    const int tid = threadIdx.x;
    const int wid = tid >> 5, lane = tid & 31;
    const int wm = wid >> 2, wn = wid & 3;
    const int bn = blockIdx.x * 128, bm = blockIdx.y * 128;
    const int KC = K >> 5;

    const f16* P[4] = { Ah + (size_t)bm * K, Am + (size_t)bm * K,
                        Bh + (size_t)bn * K, Bm + (size_t)bn * K };

    float acc[4][4][4];
#pragma unroll
    for (int i = 0; i < 4; i++)
#pragma unroll
        for (int j = 0; j < 4; j++)
#pragma unroll
            for (int q = 0; q < 4; q++) acc[i][j][q] = 0.0f;

    auto load_chunk = [&](int stage, int k0) {
#pragma unroll
        for (int t = 0; t < 4; t++) {
            const f16* src = P[t];
#pragma unroll
            for (int j = 0; j < 2; j++) {
                int ch = j * 256 + tid;
                int r = ch >> 2, cc = ch & 3;
                uint32_t off = (uint32_t)((stage * 4 + t) * DEC_TILE_B + r * 80 + cc * 16);
                cp16(su + off, src + (size_t)r * K + k0 + cc * 8);
            }
        }
        CP_COMMIT();
    };

    load_chunk(0, 0);

    const int tA[3] = {0, 0, 1};
    const int tB[3] = {2, 3, 2};

    for (int c = 0; c < KC; c++) {
        CP_WAIT0();
        __syncthreads();
        if (c + 1 < KC) load_chunk((c + 1) & 1, (c + 1) << 5);

        const int stage = c & 1;
#pragma unroll
        for (int p = 0; p < 3; p++) {
            const uint32_t baseA = su + (uint32_t)((stage * 4 + tA[p]) * DEC_TILE_B);
            const uint32_t baseB = su + (uint32_t)((stage * 4 + tB[p]) * DEC_TILE_B);
#pragma unroll
            for (int ks = 0; ks < 2; ks++) {
                uint32_t af[4][4], bg[2][4];
#pragma unroll
                for (int mt = 0; mt < 4; mt++) {
                    uint32_t addr = baseA + (uint32_t)((wm * 64 + mt * 16 + ((lane >> 3) & 1) * 8 + (lane & 7)) * 80
                                                       + (ks * 16 + (lane >> 4) * 8) * 2);
                    ldm_x4(af[mt], addr);
                }
#pragma unroll
                for (int np = 0; np < 2; np++) {
                    uint32_t addr = baseB + (uint32_t)((wn * 32 + np * 16 + ((lane >> 4) & 1) * 8 + (lane & 7)) * 80
                                                       + (ks * 16 + ((lane >> 3) & 1) * 8) * 2);
                    ldm_x4(bg[np], addr);
                }
#pragma unroll
                for (int mt = 0; mt < 4; mt++)
#pragma unroll
                    for (int nt = 0; nt < 4; nt++)
                        mma_f16(acc[mt][nt], af[mt], bg[nt >> 1][(nt & 1) * 2], bg[nt >> 1][(nt & 1) * 2 + 1]);
            }
        }
        __syncthreads();
    }

#pragma unroll
    for (int mt = 0; mt < 4; mt++) {
#pragma unroll
        for (int nt = 0; nt < 4; nt++) {
            const int r0 = bm + wm * 64 + mt * 16 + (lane >> 2);
            const int c0 = bn + wn * 32 + nt * 8 + (lane & 3) * 2;
            const float bv0 = bias[c0], bv1 = bias[c0 + 1];
#pragma unroll
            for (int h = 0; h < 2; h++) {
                const int r = r0 + h * 8;
                float v0 = acc[mt][nt][h * 2 + 0] + bv0;
                float v1 = acc[mt][nt][h * 2 + 1] + bv1;
                if (RELU) { v0 = fmaxf(v0, 0.0f); v1 = fmaxf(v1, 0.0f); }
                const size_t o = (size_t)r * N + c0;
                if (!OUTPLANES) {
                    *reinterpret_cast<float2*>(Cf + o) = make_float2(v0, v1);
                } else {
                    f16 h0 = __float2half_rn(v0), h1v = __float2half_rn(v1);
                    float r0f = v0 - __half2float(h0);
                    float r1f = v1 - __half2float(h1v);
                    __half2 hp; hp.x = h0; hp.y = h1v;
                    __half2 mp; mp.x = __float2half_rn(r0f); mp.y = __float2half_rn(r1f);
                    *reinterpret_cast<__half2*>(Ch + o) = hp;
                    *reinterpret_cast<__half2*>(Cm + o) = mp;
                }
            }
        }
    }
}

// ---------------------------------------------------------------------------
// DECODER: bf16 HMMA, 2-plane, 3-product fused (byte-identical)
// ---------------------------------------------------------------------------
template <bool RELU, int OUTP>
__global__ __launch_bounds__(256, 2)
void gemm_hmma_kernel(const bf16* __restrict__ A0, const bf16* __restrict__ A1,
                      const bf16* __restrict__ B0, const bf16* __restrict__ B1,
                      const float* __restrict__ bias,
                      float* __restrict__ Cf,
                      bf16* __restrict__ Ch, bf16* __restrict__ Cm,
                      int N, int K) {
    extern __shared__ char dsm[];
    const uint32_t su = smem_u32(dsm);

    const int tid = threadIdx.x;
    const int wid = tid >> 5, lane = tid & 31;
    const int wm = wid >> 2, wn = wid & 3;
    const int bn = blockIdx.x * 128, bm = blockIdx.y * 128;
    const int KC = K >> 5;

    const bf16* P[4] = { A0 + (size_t)bm * K, A1 + (size_t)bm * K,
                         B0 + (size_t)bn * K, B1 + (size_t)bn * K };

    float acc[4][4][4];
#pragma unroll
    for (int i = 0; i < 4; i++)
#pragma unroll
        for (int j = 0; j < 4; j++)
#pragma unroll
            for (int q = 0; q < 4; q++) acc[i][j][q] = 0.0f;

    auto load_chunk = [&](int stage, int k0) {
#pragma unroll
        for (int t = 0; t < 4; t++) {
            const bf16* src = P[t];
#pragma unroll
            for (int j = 0; j < 2; j++) {
                int ch = j * 256 + tid;
                int r = ch >> 2, cc = ch & 3;
                uint32_t off = (uint32_t)((stage * 4 + t) * DEC_TILE_B + r * 80 + cc * 16);
                cp16(su + off, src + (size_t)r * K + k0 + cc * 8);
            }
        }
        CP_COMMIT();
    };

    load_chunk(0, 0);

    const int tA[3] = {0, 0, 1};
    const int tB[3] = {2, 3, 2};

    for (int c = 0; c < KC; c++) {
        CP_WAIT0();
        __syncthreads();
        if (c + 1 < KC) load_chunk((c + 1) & 1, (c + 1) << 5);

        const int stage = c & 1;
#pragma unroll
        for (int p = 0; p < 3; p++) {
            const uint32_t baseA = su + (uint32_t)((stage * 4 + tA[p]) * DEC_TILE_B);
            const uint32_t baseB = su + (uint32_t)((stage * 4 + tB[p]) * DEC_TILE_B);
#pragma unroll
            for (int ks = 0; ks < 2; ks++) {
                uint32_t af[4][4], bg[2][4];
#pragma unroll
                for (int mt = 0; mt < 4; mt++) {
                    uint32_t addr = baseA + (uint32_t)((wm * 64 + mt * 16 + ((lane >> 3) & 1) * 8 + (lane & 7)) * 80
                                                       + (ks * 16 + (lane >> 4) * 8) * 2);
                    ldm_x4(af[mt], addr);
                }
#pragma unroll
                for (int np = 0; np < 2; np++) {
                    uint32_t addr = baseB + (uint32_t)((wn * 32 + np * 16 + ((lane >> 4) & 1) * 8 + (lane & 7)) * 80
                                                       + (ks * 16 + ((lane >> 3) & 1) * 8) * 2);
                    ldm_x4(bg[np], addr);
                }
#pragma unroll
                for (int mt = 0; mt < 4; mt++)
#pragma unroll
                    for (int nt = 0; nt < 4; nt++)
                        mma_bf16(acc[mt][nt], af[mt], bg[nt >> 1][(nt & 1) * 2], bg[nt >> 1][(nt & 1) * 2 + 1]);
            }
        }
        __syncthreads();
    }

#pragma unroll
    for (int mt = 0; mt < 4; mt++) {
#pragma unroll
        for (int nt = 0; nt < 4; nt++) {
            const int r0 = bm + wm * 64 + mt * 16 + (lane >> 2);
            const int c0 = bn + wn * 32 + nt * 8 + (lane & 3) * 2;
            const float bv0 = bias[c0], bv1 = bias[c0 + 1];
#pragma unroll
            for (int h = 0; h < 2; h++) {
                const int r = r0 + h * 8;
                float v0 = acc[mt][nt][h * 2 + 0] + bv0;
                float v1 = acc[mt][nt][h * 2 + 1] + bv1;
                if (RELU) { v0 = fmaxf(v0, 0.0f); v1 = fmaxf(v1, 0.0f); }
                const size_t o = (size_t)r * N + c0;
                if (OUTP == 0) {
                    *reinterpret_cast<float2*>(Cf + o) = make_float2(v0, v1);
                } else {
                    bf16 h0 = __float2bfloat16(v0), h1v = __float2bfloat16(v1);
                    float r0f = v0 - __bfloat162float(h0);
                    float r1f = v1 - __bfloat162float(h1v);
                    __nv_bfloat162 hp; hp.x = h0; hp.y = h1v;
                    __nv_bfloat162 mp; mp.x = __float2bfloat16(r0f); mp.y = __float2bfloat16(r1f);
                    *reinterpret_cast<__nv_bfloat162*>(Ch + o) = hp;
                    *reinterpret_cast<__nv_bfloat162*>(Cm + o) = mp;
                }
            }
        }
    }
}

// ---------------------------------------------------------------------------
// Splits
// ---------------------------------------------------------------------------
__global__ void split2h_kernel(const float* __restrict__ src,
                               f16* __restrict__ h, f16* __restrict__ m, int n) {
    int i = blockIdx.x * blockDim.x + threadIdx.x;
    if (i < n) {
        float v = src[i];
        f16 a = __float2half_rn(v);
        float r1 = v - __half2float(a);
        h[i] = a; m[i] = __float2half_rn(r1);
    }
}
__global__ void split2_kernel(const float* __restrict__ src,
                              bf16* __restrict__ h, bf16* __restrict__ m, int n) {
    int i = blockIdx.x * blockDim.x + threadIdx.x;
    if (i < n) {
        float v = src[i];
        bf16 a = __float2bfloat16(v);
        float r1 = v - __bfloat162float(a);
        h[i] = a; m[i] = __float2bfloat16(r1);
    }
}

// ---------------------------------------------------------------------------
// Codebook squared norms
// ---------------------------------------------------------------------------
__global__ void cnorm_kernel(const float* __restrict__ cb, float* __restrict__ cn) {
    int i = blockIdx.x * blockDim.x + threadIdx.x;
    if (i >= EMB_NUM) return;
    const float4* p = reinterpret_cast<const float4*>(cb + (size_t)i * EMB_DIM);
    float s = 0.0f;
#pragma unroll
    for (int d = 0; d < EMB_DIM / 4; d++) {
        float4 v = p[d];
        s += v.x * v.x + v.y * v.y + v.z * v.z + v.w * v.w;
    }
    cn[i] = s;
}

// ---------------------------------------------------------------------------
// VQ with gap test (byte-identical to round 12)
// ---------------------------------------------------------------------------
__global__ __launch_bounds__(256)
void vq_kernel(const float* __restrict__ z,
               const float* __restrict__ cb,
               const float* __restrict__ cn,
               bf16* __restrict__ qh, bf16* __restrict__ qm,
               int* __restrict__ flags) {
    constexpr int CHUNK = 128;
    __shared__ float sc[CHUNK][EMB_DIM];
    __shared__ float scn[CHUNK];

    const int row = blockIdx.x * blockDim.x + threadIdx.x;
    const float* zp = z + (size_t)row * EMB_DIM;

    u64 m2zP[EMB_DIM / 2];
#pragma unroll
    for (int d = 0; d < EMB_DIM / 4; d++) {
        float4 v = reinterpret_cast<const float4*>(zp)[d];
        m2zP[d * 2 + 0] = pack2f(-2.0f * v.x, -2.0f * v.y);
        m2zP[d * 2 + 1] = pack2f(-2.0f * v.z, -2.0f * v.w);
    }

    float best = 3.0e38f, best2 = 3.0e38f;
    int bidx = 0;
    for (int ch = 0; ch < EMB_NUM / CHUNK; ch++) {
        __syncthreads();
        const float4* src = reinterpret_cast<const float4*>(cb + (size_t)ch * CHUNK * EMB_DIM);
        float4* dst = reinterpret_cast<float4*>(&sc[0][0]);
        for (int i = threadIdx.x; i < CHUNK * EMB_DIM / 4; i += 256) dst[i] = src[i];
        if (threadIdx.x < CHUNK) scn[threadIdx.x] = cn[ch * CHUNK + threadIdx.x];
        __syncthreads();

        for (int j = 0; j < CHUNK; j++) {
            const u64* cc8 = reinterpret_cast<const u64*>(&sc[j][0]);
            u64 sP = 0ull;
#pragma unroll
            for (int d = 0; d < EMB_DIM / 2; d++)
                sP = ffma2(cc8[d], m2zP[d], sP);
            float lo, hi;
            unpack2f(sP, lo, hi);
            float s = scn[j] + lo + hi;
            if (s < best) { best2 = best; best = s; bidx = ch * CHUNK + j; }
            else if (s < best2) { best2 = s; }
        }
    }

    flags[row] = (best2 - best < FLAG_T) ? 1 : 0;

    const float* cp = cb + (size_t)bidx * EMB_DIM;
#pragma unroll
    for (int d = 0; d < EMB_DIM; d++) {
        float zz = zp[d];
        float v = zz + (cp[d] - zz);
        bf16 a = __float2bfloat16(v);
        float r1 = v - __bfloat162float(a);
        size_t o = (size_t)row * EMB_DIM + d;
        qh[o] = a; qm[o] = __float2bfloat16(r1);
    }
}

// ---------------------------------------------------------------------------
// Repair list: reset + compact flagged x-rows
// ---------------------------------------------------------------------------
__global__ void rep_reset_kernel(int* nrep) { *nrep = 0; }

__global__ void rep_compact_kernel(const int* __restrict__ flags,
                                   int* __restrict__ rlist, int* __restrict__ nrep) {
    int row = blockIdx.x * blockDim.x + threadIdx.x;
    if (row >= M_ROWS) return;
    const int f = flags[row * 4 + 0] | flags[row * 4 + 1] | flags[row * 4 + 2] | flags[row * 4 + 3];
    if (f) {
        int pos = atomicAdd(nrep, 1);
        if (pos < REP_CAP) rlist[pos] = row;
    }
}

// ---------------------------------------------------------------------------
// Batched repair phase 1: exact h1 for listed rows. 8 rows per CTA pass,
// thread t owns output (blockIdx.x*256 + t), ascending-k fmaf per output
// (bitwise identical to per-row path).
// ---------------------------------------------------------------------------
__global__ __launch_bounds__(256)
void rep_h1_kernel(const float* __restrict__ x,
                   const float* __restrict__ w0, const float* __restrict__ b0,
                   const int* __restrict__ rlist, const int* __restrict__ nrep,
                   float* __restrict__ rh1) {
    __shared__ float xs[8][2048];
    const int nr = min(*nrep, REP_CAP);
    const int t = threadIdx.x;
    const int out = blockIdx.x * 256 + t;
    const float* wr = w0 + (size_t)out * 2048;
    const float bb = b0[out];

    for (int base = blockIdx.y * 8; base < nr; base += gridDim.y * 8) {
        const int cnt = min(8, nr - base);
        __syncthreads();
        for (int r = 0; r < cnt; r++) {
            const float4* xr = reinterpret_cast<const float4*>(x + (size_t)rlist[base + r] * 2048);
            float4* xd = reinterpret_cast<float4*>(xs[r]);
            for (int i = t; i < 512; i += 256) xd[i] = xr[i];
        }
        __syncthreads();
        float acc[8];
#pragma unroll
        for (int r = 0; r < 8; r++) acc[r] = 0.0f;
        for (int k = 0; k < 2048; k += 4) {
            float4 wv = *reinterpret_cast<const float4*>(wr + k);
#pragma unroll
            for (int r = 0; r < 8; r++) {
                float4 xv = *reinterpret_cast<const float4*>(&xs[r][k]);
                acc[r] = fmaf(xv.x, wv.x, acc[r]);
                acc[r] = fmaf(xv.y, wv.y, acc[r]);
                acc[r] = fmaf(xv.z, wv.z, acc[r]);
                acc[r] = fmaf(xv.w, wv.w, acc[r]);
            }
        }
        for (int r = 0; r < cnt; r++)
            rh1[(size_t)(base + r) * 1024 + out] = fmaxf(acc[r] + bb, 0.0f);
    }
}

// ---------------------------------------------------------------------------
// Batched repair phase 2: exact h2 from rh1.
// ---------------------------------------------------------------------------
__global__ __launch_bounds__(256)
void rep_h2_kernel(const float* __restrict__ w1, const float* __restrict__ b1,
                   const int* __restrict__ nrep,
                   const float* __restrict__ rh1, float* __restrict__ rh2) {
    __shared__ float hs[8][1024];
    const int nr = min(*nrep, REP_CAP);
    const int t = threadIdx.x;
    const int out = blockIdx.x * 256 + t;
    const float* wr = w1 + (size_t)out * 1024;
    const float bb = b1[out];

    for (int base = blockIdx.y * 8; base < nr; base += gridDim.y * 8) {
        const int cnt = min(8, nr - base);
        __syncthreads();
        for (int r = 0; r < cnt; r++) {
            const float4* hr = reinterpret_cast<const float4*>(rh1 + (size_t)(base + r) * 1024);
            float4* hd = reinterpret_cast<float4*>(hs[r]);
            for (int i = t; i < 256; i += 256) hd[i] = hr[i];
        }
        __syncthreads();
        float acc[8];
#pragma unroll
        for (int r = 0; r < 8; r++) acc[r] = 0.0f;
        for (int k = 0; k < 1024; k += 4) {
            float4 wv = *reinterpret_cast<const float4*>(wr + k);
#pragma unroll
            for (int r = 0; r < 8; r++) {
                float4 hv = *reinterpret_cast<const float4*>(&hs[r][k]);
                acc[r] = fmaf(hv.x, wv.x, acc[r]);
                acc[r] = fmaf(hv.y, wv.y, acc[r]);
                acc[r] = fmaf(hv.z, wv.z, acc[r]);
                acc[r] = fmaf(hv.w, wv.w, acc[r]);
            }
        }
        for (int r = 0; r < cnt; r++)
            rh2[(size_t)(base + r) * 512 + out] = fmaxf(acc[r] + bb, 0.0f);
    }
}

// ---------------------------------------------------------------------------
// Batched repair phase 3: exact z, exact argmin (flagged groups), write zq.
// One listed row per CTA iteration (256 threads).
// ---------------------------------------------------------------------------
__global__ __launch_bounds__(256)
void rep_z_kernel(const float* __restrict__ zw, const float* __restrict__ zb,
                  const float* __restrict__ cb, const float* __restrict__ cn,
                  const int* __restrict__ rlist, const int* __restrict__ nrep,
                  const int* __restrict__ flags,
                  const float* __restrict__ rh2,
                  bf16* __restrict__ qh, bf16* __restrict__ qm) {
    __shared__ float h2s[512];
    __shared__ float zs[256];
    __shared__ float rbest[256];
    __shared__ int ridx[256];
    const int nr = min(*nrep, REP_CAP);
    const int t = threadIdx.x;

    for (int pos = blockIdx.x; pos < nr; pos += gridDim.x) {
        const int row = rlist[pos];
        __syncthreads();
        {
            const float4* hr = reinterpret_cast<const float4*>(rh2 + (size_t)pos * 512);
            float4* hd = reinterpret_cast<float4*>(h2s);
            for (int i = t; i < 128; i += 256) hd[i] = hr[i];
        }
        __syncthreads();
        {
            const float* wr = zw + (size_t)t * 512;
            float acc = 0.0f;
            for (int k = 0; k < 512; k += 4) {
                float4 hv = *reinterpret_cast<const float4*>(h2s + k);
                float4 wv = *reinterpret_cast<const float4*>(wr + k);
                acc = fmaf(hv.x, wv.x, acc); acc = fmaf(hv.y, wv.y, acc);
                acc = fmaf(hv.z, wv.z, acc); acc = fmaf(hv.w, wv.w, acc);
            }
            zs[t] = acc + zb[t];
        }
        __syncthreads();

#pragma unroll
        for (int g = 0; g < 4; g++) {
            if (!flags[row * 4 + g]) continue;
            const float* zg = zs + g * EMB_DIM;
            u64 m2zP[EMB_DIM / 2];
#pragma unroll
            for (int d = 0; d < EMB_DIM / 4; d++) {
                float4 v = *reinterpret_cast<const float4*>(zg + d * 4);
                m2zP[d * 2 + 0] = pack2f(-2.0f * v.x, -2.0f * v.y);
                m2zP[d * 2 + 1] = pack2f(-2.0f * v.z, -2.0f * v.w);
            }
            float best = 3.0e38f;
            int bidx = 0;
            for (int jj = 0; jj < 4; jj++) {
                int j = jj * 256 + t;
                u64 sP = 0ull;
                const u64* cc8 = reinterpret_cast<const u64*>(cb + (size_t)j * EMB_DIM);
#pragma unroll
                for (int d = 0; d < EMB_DIM / 2; d++)
                    sP = ffma2(cc8[d], m2zP[d], sP);
                float lo, hi;
                unpack2f(sP, lo, hi);
                float s = cn[j] + lo + hi;
                if (s < best || (s == best && j < bidx)) { best = s; bidx = j; }
            }
            rbest[t] = best; ridx[t] = bidx;
            __syncthreads();
            for (int s2 = 128; s2 > 0; s2 >>= 1) {
                if (t < s2) {
                    float ob = rbest[t + s2]; int oi = ridx[t + s2];
                    if (ob < rbest[t] || (ob == rbest[t] && oi < ridx[t])) { rbest[t] = ob; ridx[t] = oi; }
                }
                __syncthreads();
            }
            const int fin = ridx[0];
            if (t < EMB_DIM) {
                float zz = zg[t];
                float v = zz + (cb[(size_t)fin * EMB_DIM + t] - zz);
                bf16 a = __float2bfloat16(v);
                float r1 = v - __bfloat162float(a);
                size_t o = ((size_t)row * 4 + g) * EMB_DIM + t;
                qh[o] = a; qm[o] = __float2bfloat16(r1);
            }
            __syncthreads();
        }
    }
}

// ---------------------------------------------------------------------------
// FALLBACK per-row repair: only active if nrep > REP_CAP (idempotent redo).
// (proven round-10/12 code, plus the nrep gate)
// ---------------------------------------------------------------------------
__global__ __launch_bounds__(256)
void repair_kernel(const float* __restrict__ x,
                   const float* __restrict__ w0, const float* __restrict__ b0,
                   const float* __restrict__ w1, const float* __restrict__ b1,
                   const float* __restrict__ zw, const float* __restrict__ zb,
                   const float* __restrict__ cb, const float* __restrict__ cn,
                   const int* __restrict__ flags, const int* __restrict__ nrep,
                   bf16* __restrict__ qh, bf16* __restrict__ qm) {
    if (*nrep <= REP_CAP) return;
    const int row = blockIdx.x;
    const int f0 = flags[row * 4 + 0], f1 = flags[row * 4 + 1];
    const int f2 = flags[row * 4 + 2], f3 = flags[row * 4 + 3];
    if (!(f0 | f1 | f2 | f3)) return;

    __shared__ float xs[2048];
    __shared__ float h1s[1024];
    __shared__ float h2s[512];
    __shared__ float zs[256];
    __shared__ float rbest[256];
    __shared__ int ridx[256];

    const int t = threadIdx.x;

    {
        const float4* xr = reinterpret_cast<const float4*>(x + (size_t)row * 2048);
        float4* xd = reinterpret_cast<float4*>(xs);
        for (int i = t; i < 512; i += 256) xd[i] = xr[i];
    }
    __syncthreads();

    {
        const float* r0 = w0 + (size_t)(t      ) * 2048;
        const float* r1 = w0 + (size_t)(t + 256) * 2048;
        const float* r2 = w0 + (size_t)(t + 512) * 2048;
        const float* r3 = w0 + (size_t)(t + 768) * 2048;
        float a0 = 0.0f, a1 = 0.0f, a2 = 0.0f, a3 = 0.0f;
        for (int k = 0; k < 2048; k += 4) {
            float4 xv = *reinterpret_cast<const float4*>(xs + k);
            float4 v0 = *reinterpret_cast<const float4*>(r0 + k);
            float4 v1 = *reinterpret_cast<const float4*>(r1 + k);
            float4 v2 = *reinterpret_cast<const float4*>(r2 + k);
            float4 v3 = *reinterpret_cast<const float4*>(r3 + k);
            a0 = fmaf(xv.x, v0.x, a0); a0 = fmaf(xv.y, v0.y, a0);
            a0 = fmaf(xv.z, v0.z, a0); a0 = fmaf(xv.w, v0.w, a0);
            a1 = fmaf(xv.x, v1.x, a1); a1 = fmaf(xv.y, v1.y, a1);
            a1 = fmaf(xv.z, v1.z, a1); a1 = fmaf(xv.w, v1.w, a1);
            a2 = fmaf(xv.x, v2.x, a2); a2 = fmaf(xv.y, v2.y, a2);
            a2 = fmaf(xv.z, v2.z, a2); a2 = fmaf(xv.w, v2.w, a2);
            a3 = fmaf(xv.x, v3.x, a3); a3 = fmaf(xv.y, v3.y, a3);
            a3 = fmaf(xv.z, v3.z, a3); a3 = fmaf(xv.w, v3.w, a3);
        }
        h1s[t      ] = fmaxf(a0 + b0[t      ], 0.0f);
        h1s[t + 256] = fmaxf(a1 + b0[t + 256], 0.0f);
        h1s[t + 512] = fmaxf(a2 + b0[t + 512], 0.0f);
        h1s[t + 768] = fmaxf(a3 + b0[t + 768], 0.0f);
    }
    __syncthreads();

    {
        const float* r0 = w1 + (size_t)(t      ) * 1024;
        const float* r1 = w1 + (size_t)(t + 256) * 1024;
        float a0 = 0.0f, a1 = 0.0f;
        for (int k = 0; k < 1024; k += 4) {
            float4 hv = *reinterpret_cast<const float4*>(h1s + k);
            float4 v0 = *reinterpret_cast<const float4*>(r0 + k);
            float4 v1 = *reinterpret_cast<const float4*>(r1 + k);
            a0 = fmaf(hv.x, v0.x, a0); a0 = fmaf(hv.y, v0.y, a0);
            a0 = fmaf(hv.z, v0.z, a0); a0 = fmaf(hv.w, v0.w, a0);
            a1 = fmaf(hv.x, v1.x, a1); a1 = fmaf(hv.y, v1.y, a1);
            a1 = fmaf(hv.z, v1.z, a1); a1 = fmaf(hv.w, v1.w, a1);
        }
        h2s[t      ] = fmaxf(a0 + b1[t      ], 0.0f);
        h2s[t + 256] = fmaxf(a1 + b1[t + 256], 0.0f);
    }
    __syncthreads();

    {
        const float* wr = zw + (size_t)t * 512;
        float acc = 0.0f;
        for (int k = 0; k < 512; k += 4) {
            float4 hv = *reinterpret_cast<const float4*>(h2s + k);
            float4 wv = *reinterpret_cast<const float4*>(wr + k);
            acc = fmaf(hv.x, wv.x, acc); acc = fmaf(hv.y, wv.y, acc);
            acc = fmaf(hv.z, wv.z, acc); acc = fmaf(hv.w, wv.w, acc);
        }
        zs[t] = acc + zb[t];
    }
    __syncthreads();

    const int gf[4] = {f0, f1, f2, f3};
#pragma unroll
    for (int g = 0; g < 4; g++) {
        if (!gf[g]) continue;
        const float* zg = zs + g * EMB_DIM;
        u64 m2zP[EMB_DIM / 2];
#pragma unroll
        for (int d = 0; d < EMB_DIM / 4; d++) {
            float4 v = *reinterpret_cast<const float4*>(zg + d * 4);
            m2zP[d * 2 + 0] = pack2f(-2.0f * v.x, -2.0f * v.y);
            m2zP[d * 2 + 1] = pack2f(-2.0f * v.z, -2.0f * v.w);
        }
        float best = 3.0e38f;
        int bidx = 0;
        for (int jj = 0; jj < 4; jj++) {
            int j = jj * 256 + t;
            u64 sP = 0ull;
            const u64* cc8 = reinterpret_cast<const u64*>(cb + (size_t)j * EMB_DIM);
#pragma unroll
            for (int d = 0; d < EMB_DIM / 2; d++)
                sP = ffma2(cc8[d], m2zP[d], sP);
            float lo, hi;
            unpack2f(sP, lo, hi);
            float s = cn[j] + lo + hi;
            if (s < best || (s == best && j < bidx)) { best = s; bidx = j; }
        }
        rbest[t] = best; ridx[t] = bidx;
        __syncthreads();
        for (int s2 = 128; s2 > 0; s2 >>= 1) {
            if (t < s2) {
                float ob = rbest[t + s2]; int oi = ridx[t + s2];
                if (ob < rbest[t] || (ob == rbest[t] && oi < ridx[t])) { rbest[t] = ob; ridx[t] = oi; }
            }
            __syncthreads();
        }
        const int fin = ridx[0];
        if (t < EMB_DIM) {
            float zz = zg[t];
            float v = zz + (cb[(size_t)fin * EMB_DIM + t] - zz);
            bf16 a = __float2bfloat16(v);
            float r1 = v - __bfloat162float(a);
            size_t o = ((size_t)row * 4 + g) * EMB_DIM + t;
            qh[o] = a; qm[o] = __float2bfloat16(r1);
        }
        __syncthreads();
    }
}

// ---------------------------------------------------------------------------
// Host launch
// ---------------------------------------------------------------------------
template <bool RELU, bool OUTPLANES>
static inline void launch_encH(const f16* Ah, const f16* Am,
                               const f16* Bh, const f16* Bm,
                               const float* bias, float* Cf, f16* Ch, f16* Cm,
                               int N, int K) {
    cudaFuncSetAttribute(enc_hmma_kernel<RELU, OUTPLANES>,
                         cudaFuncAttributeMaxDynamicSharedMemorySize, DEC_SMEM);
    dim3 grid(N / 128, M_ROWS / 128);
    enc_hmma_kernel<RELU, OUTPLANES><<<grid, 256, DEC_SMEM>>>(Ah, Am, Bh, Bm, bias, Cf, Ch, Cm, N, K);
}

template <bool RELU, int OUTP>
static inline void launch_dec(const bf16* A0, const bf16* A1,
                              const bf16* B0, const bf16* B1,
                              const float* bias, float* Cf, bf16* Ch, bf16* Cm,
                              int N, int K) {
    cudaFuncSetAttribute(gemm_hmma_kernel<RELU, OUTP>,
                         cudaFuncAttributeMaxDynamicSharedMemorySize, DEC_SMEM);
    dim3 grid(N / 128, M_ROWS / 128);
    gemm_hmma_kernel<RELU, OUTP><<<grid, 256, DEC_SMEM>>>(A0, A1, B0, B1, bias, Cf, Ch, Cm, N, K);
}

extern "C" void kernel_launch(void* const* d_in, const int* in_sizes, int n_in,
                              void* d_out, int out_size) {
    const float* x        = (const float*)d_in[0];
    const float* enc0_w   = (const float*)d_in[1];
    const float* enc0_b   = (const float*)d_in[2];
    const float* enc1_w   = (const float*)d_in[3];
    const float* enc1_b   = (const float*)d_in[4];
    const float* z_w      = (const float*)d_in[5];
    const float* z_b      = (const float*)d_in[6];
    const float* codebook = (const float*)d_in[7];
    const float* dec0_w   = (const float*)d_in[8];
    const float* dec0_b   = (const float*)d_in[9];
    const float* dec1_w   = (const float*)d_in[10];
    const float* dec1_b   = (const float*)d_in[11];
    const float* out_w    = (const float*)d_in[12];
    const float* out_b    = (const float*)d_in[13];
    float* out = (float*)d_out;

    f16 *xh, *xm, *w0h, *w0m, *w1h, *w1m, *wzh, *wzm, *h1h, *h1m, *h2h, *h2m;
    cudaGetSymbolAddress((void**)&xh, g_xh);
    cudaGetSymbolAddress((void**)&xm, g_xm);
    cudaGetSymbolAddress((void**)&w0h, g_w0h);
    cudaGetSymbolAddress((void**)&w0m, g_w0m);
    cudaGetSymbolAddress((void**)&w1h, g_w1h);
    cudaGetSymbolAddress((void**)&w1m, g_w1m);
    cudaGetSymbolAddress((void**)&wzh, g_wzh);
    cudaGetSymbolAddress((void**)&wzm, g_wzm);
    cudaGetSymbolAddress((void**)&h1h, g_h1h);
    cudaGetSymbolAddress((void**)&h1m, g_h1m);
    cudaGetSymbolAddress((void**)&h2h, g_h2h);
    cudaGetSymbolAddress((void**)&h2m, g_h2m);
    float *z, *cn, *rh1, *rh2;
    int *flags, *rlist, *nrep;
    cudaGetSymbolAddress((void**)&z,  g_z);
    cudaGetSymbolAddress((void**)&cn, g_cn);
    cudaGetSymbolAddress((void**)&flags, g_flags);
    cudaGetSymbolAddress((void**)&rlist, g_rlist);
    cudaGetSymbolAddress((void**)&nrep, g_nrep);
    cudaGetSymbolAddress((void**)&rh1, g_rh1);
    cudaGetSymbolAddress((void**)&rh2, g_rh2);
    bf16 (*zq)[8192 * 256];   cudaGetSymbolAddress((void**)&zq, g_zq);
    bf16 (*d1)[8192 * 512];   cudaGetSymbolAddress((void**)&d1, g_d1);
    bf16 (*d2)[8192 * 1024];  cudaGetSymbolAddress((void**)&d2, g_d2);
    bf16 (*wd0)[512 * 256];   cudaGetSymbolAddress((void**)&wd0, g_wd0);
    bf16 (*wd1)[1024 * 512];  cudaGetSymbolAddress((void**)&wd1, g_wd1);
    bf16 (*wo)[2048 * 1024];  cudaGetSymbolAddress((void**)&wo, g_wo);

    // splits
    split2h_kernel<<<(8192 * 2048 + 255) / 256, 256>>>(x, xh, xm, 8192 * 2048);
    split2h_kernel<<<(1024 * 2048 + 255) / 256, 256>>>(enc0_w, w0h, w0m, 1024 * 2048);
    split2h_kernel<<<(512 * 1024 + 255) / 256, 256>>>(enc1_w, w1h, w1m, 512 * 1024);
    split2h_kernel<<<(256 * 512 + 255) / 256, 256>>>(z_w, wzh, wzm, 256 * 512);
    split2_kernel<<<(512 * 256 + 255) / 256, 256>>>(dec0_w, wd0[0], wd0[1], 512 * 256);
    split2_kernel<<<(1024 * 512 + 255) / 256, 256>>>(dec1_w, wd1[0], wd1[1], 1024 * 512);
    split2_kernel<<<(2048 * 1024 + 255) / 256, 256>>>(out_w, wo[0], wo[1], 2048 * 1024);

    // encoder: h1, h2, z all via fp16 HMMA
    launch_encH<true, true >(xh, xm, w0h, w0m, enc0_b, nullptr, h1h, h1m, 1024, 2048);
    launch_encH<true, true >(h1h, h1m, w1h, w1m, enc1_b, nullptr, h2h, h2m, 512, 1024);
    launch_encH<false, false>(h2h, h2m, wzh, wzm, z_b, z, nullptr, nullptr, 256, 512);

    // vector quantization with gap test
    cnorm_kernel<<<4, 256>>>(codebook, cn);
    rep_reset_kernel<<<1, 1>>>(nrep);
    vq_kernel<<<(M_ROWS * 256 / EMB_DIM) / 256, 256>>>(z, codebook, cn, zq[0], zq[1], flags);

    // batched exact repair of flagged rows
    rep_compact_kernel<<<M_ROWS / 256, 256>>>(flags, rlist, nrep);
    { dim3 g1(4, 16);  rep_h1_kernel<<<g1, 256>>>(x, enc0_w, enc0_b, rlist, nrep, rh1); }
    { dim3 g2(2, 16);  rep_h2_kernel<<<g2, 256>>>(enc1_w, enc1_b, nrep, rh1, rh2); }
    rep_z_kernel<<<64, 256>>>(z_w, z_b, codebook, cn, rlist, nrep, flags, rh2, zq[0], zq[1]);
    // fallback (no-op unless nrep > REP_CAP)
    repair_kernel<<<M_ROWS, 256>>>(x, enc0_w, enc0_b, enc1_w, enc1_b, z_w, z_b,
                                   codebook, cn, flags, nrep, zq[0], zq[1]);

    // decoder (unchanged)
    launch_dec<true,  2>(zq[0], zq[1], wd0[0], wd0[1], dec0_b, nullptr, d1[0], d1[1], 512, 256);
    launch_dec<true,  2>(d1[0], d1[1], wd1[0], wd1[1], dec1_b, nullptr, d2[0], d2[1], 1024, 512);
    launch_dec<false, 0>(d2[0], d2[1], wo[0], wo[1],  out_b,  out, nullptr, nullptr, 2048, 1024);
}